// round 1
// baseline (speedup 1.0000x reference)
#include <cuda_runtime.h>
#include <cuda_bf16.h>
#include <math.h>

// Problem shapes (fixed)
#define B_ 4
#define N_ 4096
#define W_ 1024
#define H_ 16
#define A_ 64
#define HA_ 1024           // H_*A_
#define M_ 16384           // B_*N_

// ---------------------------------------------------------------------------
// Scratch (no allocations allowed -> __device__ globals)
// ---------------------------------------------------------------------------
__device__ float g_values[M_ * HA_];        // [b,n,h,a]  64 MB
__device__ float g_outbuf[M_ * HA_];        // [b,n,h,a]  64 MB
__device__ float g_wv_t[W_ * HA_];          // [w][h*A+a]  4 MB
__device__ float g_wo_t[HA_ * W_];          // [h*A+a][w]  4 MB
__device__ float g_cross[B_ * H_ * N_];     // exp'd, [b,h,n]
__device__ float g_diag [B_ * H_ * N_];
__device__ float g_extra[B_ * H_ * N_];
__device__ float g_p1 [H_ * N_];
__device__ float g_p2e[H_ * N_];            // exp'd
__device__ float g_psum_cv[B_ * H_ * 32 * A_]; // chunk partials (cross*values)
__device__ float g_psum_c [B_ * H_ * 32];      // chunk partials (cross)

// ---------------------------------------------------------------------------
// 1) Weight re-layout:  Wv_t[w][h*A+a] = vw[h,w,a];  Wo_t[h*A+a][w] = ow[h,w,a]
// ---------------------------------------------------------------------------
__global__ void transpose_weights(const float* __restrict__ vw,
                                  const float* __restrict__ ow) {
    int idx = blockIdx.x * blockDim.x + threadIdx.x;   // 0 .. 1024*1024-1
    // g_wv_t: idx = w*1024 + (h*64+a)
    {
        int w = idx >> 10;
        int n = idx & 1023;
        int h = n >> 6;
        int a = n & 63;
        g_wv_t[idx] = vw[(h * W_ + w) * A_ + a];
    }
    // g_wo_t: idx = (h*64+a)*1024 + w
    {
        int k = idx >> 10;
        int w = idx & 1023;
        int h = k >> 6;
        int a = k & 63;
        g_wo_t[idx] = ow[(h * W_ + w) * A_ + a];
    }
}

// ---------------------------------------------------------------------------
// 2) Positional: p1[h,n] = sum_p sin(a1*nv+b1)*c ;  p2e = exp(clip(p2))
// ---------------------------------------------------------------------------
__global__ void pos_kernel(const float* __restrict__ a1, const float* __restrict__ a2,
                           const float* __restrict__ b1, const float* __restrict__ b2,
                           const float* __restrict__ cc) {
    int idx = blockIdx.x * blockDim.x + threadIdx.x;   // h*N + n
    int h = idx >> 12;
    int n = idx & (N_ - 1);
    float nv = (float)n * (1.0f / 4095.0f);
    float s1 = 0.f, s2 = 0.f;
#pragma unroll 8
    for (int p = 0; p < 64; p++) {
        float cp = cc[h * 64 + p];
        s1 += sinf(fmaf(a1[h * 64 + p], nv, b1[h * 64 + p])) * cp;
        s2 += sinf(fmaf(a2[h * 64 + p], nv, b2[h * 64 + p])) * cp;
    }
    g_p1[idx] = s1;
    s2 = fminf(fmaxf(s2, -20.f), 20.f);
    g_p2e[idx] = expf(s2);
}

// ---------------------------------------------------------------------------
// 3) Projections: per row (b,n): 48 dots of length 1024 with k1/k2/k3 per h,
//    add p1 for cross, clip-exp, store [b,h,n].
// ---------------------------------------------------------------------------
__global__ __launch_bounds__(256) void proj_kernel(const float* __restrict__ x,
                                                   const float* __restrict__ k1,
                                                   const float* __restrict__ k2,
                                                   const float* __restrict__ k3) {
    __shared__ float xs[W_];
    int row = blockIdx.x;                 // b*N + n
    const float4* xr = (const float4*)(x + (size_t)row * W_);
    float4* xs4 = (float4*)xs;
    xs4[threadIdx.x] = xr[threadIdx.x];   // 256 float4 = 1024 floats
    __syncthreads();

    int warp = threadIdx.x >> 5;
    int lane = threadIdx.x & 31;
    int b = row >> 12;
    int n = row & (N_ - 1);

    for (int j = warp; j < 48; j += 8) {
        int which = j >> 4;               // 0=k1,1=k2,2=k3
        int h = j & 15;
        const float* kk = (which == 0) ? k1 : ((which == 1) ? k2 : k3);
        const float* kh = kk + h * W_;
        float s = 0.f;
#pragma unroll 8
        for (int i = lane; i < W_; i += 32) s += xs[i] * kh[i];
#pragma unroll
        for (int o = 16; o; o >>= 1) s += __shfl_xor_sync(0xffffffffu, s, o);
        if (lane == 0) {
            if (which == 0) s += g_p1[h * N_ + n];
            s = fminf(fmaxf(s, -20.f), 20.f);
            s = expf(s);
            int off = (b * H_ + h) * N_ + n;
            if (which == 0)      g_cross[off] = s;
            else if (which == 1) g_diag[off]  = s;
            else                 g_extra[off] = s;
        }
    }
}

// ---------------------------------------------------------------------------
// 4/7) SGEMM: C[M,1024] = A[M,1024] @ Bm[1024,1024], all row-major fp32.
//    128x128 block tile, BK=8, 256 threads, 8x8 per thread.
// ---------------------------------------------------------------------------
__global__ __launch_bounds__(256) void sgemm(const float* __restrict__ A,
                                             const float* __restrict__ Bm,
                                             float* __restrict__ C) {
    const int K = 1024, Nn = 1024;
    __shared__ float As[8][128];
    __shared__ float Bs[8][128];

    int tid = threadIdx.x;
    int bm = blockIdx.y, bn = blockIdx.x;

    A += (size_t)bm * 128 * K;
    Bm += bn * 128;
    C += (size_t)bm * 128 * Nn + bn * 128;

    int arow = tid >> 1;            // 0..127
    int acol = (tid & 1) * 4;       // 0 or 4
    int brow = tid >> 5;            // 0..7
    int bcol = (tid & 31) * 4;      // 0..124

    int ty = tid >> 4;              // 0..15
    int tx = tid & 15;              // 0..15

    float acc[8][8];
#pragma unroll
    for (int i = 0; i < 8; i++)
#pragma unroll
        for (int j = 0; j < 8; j++) acc[i][j] = 0.f;

    for (int k0 = 0; k0 < K; k0 += 8) {
        float4 av = *(const float4*)(A + (size_t)arow * K + k0 + acol);
        As[acol + 0][arow] = av.x;
        As[acol + 1][arow] = av.y;
        As[acol + 2][arow] = av.z;
        As[acol + 3][arow] = av.w;
        float4 bv = *(const float4*)(Bm + (size_t)(k0 + brow) * Nn + bcol);
        *(float4*)(&Bs[brow][bcol]) = bv;
        __syncthreads();

#pragma unroll
        for (int kk = 0; kk < 8; kk++) {
            float ar[8], br[8];
#pragma unroll
            for (int i = 0; i < 8; i++) ar[i] = As[kk][ty * 8 + i];
#pragma unroll
            for (int j = 0; j < 8; j++) br[j] = Bs[kk][tx * 8 + j];
#pragma unroll
            for (int i = 0; i < 8; i++)
#pragma unroll
                for (int j = 0; j < 8; j++) acc[i][j] = fmaf(ar[i], br[j], acc[i][j]);
        }
        __syncthreads();
    }

#pragma unroll
    for (int i = 0; i < 8; i++)
#pragma unroll
        for (int j = 0; j < 8; j += 4) {
            *(float4*)(&C[(size_t)(ty * 8 + i) * Nn + tx * 8 + j]) =
                make_float4(acc[i][j], acc[i][j + 1], acc[i][j + 2], acc[i][j + 3]);
        }
}

// ---------------------------------------------------------------------------
// 5) Scan phase 1: per (bh, chunk of 128 n): partial sums of cross and cross*v
// ---------------------------------------------------------------------------
__global__ void scan_partial() {
    int bh = blockIdx.y;                // b*16+h
    int ch = blockIdx.x;                // 0..31
    int a = threadIdx.x;                // 0..63
    int b = bh >> 4, h = bh & 15;
    const float* cr = g_cross + bh * N_;
    int n0 = ch * 128;
    float sc = 0.f, scv = 0.f;
#pragma unroll 4
    for (int i = 0; i < 128; i++) {
        int n = n0 + i;
        float cn = cr[n];
        float v = g_values[((size_t)(b * N_ + n) * H_ + h) * A_ + a];
        sc += cn;
        scv = fmaf(cn, v, scv);
    }
    g_psum_cv[(bh * 32 + ch) * A_ + a] = scv;
    if (a == 0) g_psum_c[bh * 32 + ch] = sc;
}

// ---------------------------------------------------------------------------
// 6) Scan phase 2: exclusive prefix over the 32 chunks (tiny)
// ---------------------------------------------------------------------------
__global__ void scan_prefix() {
    int bh = blockIdx.x;
    int a = threadIdx.x;
    float run = 0.f;
    for (int ch = 0; ch < 32; ch++) {
        int idx = (bh * 32 + ch) * A_ + a;
        float v = g_psum_cv[idx];
        g_psum_cv[idx] = run;
        run += v;
    }
    if (a == 0) {
        float rc = 0.f;
        for (int ch = 0; ch < 32; ch++) {
            float v = g_psum_c[bh * 32 + ch];
            g_psum_c[bh * 32 + ch] = rc;
            rc += v;
        }
    }
}

// ---------------------------------------------------------------------------
// 7) Scan phase 3: rescan chunk with carried prefix; write out[b,n,h,a]
// ---------------------------------------------------------------------------
__global__ void scan_final() {
    int bh = blockIdx.y;
    int ch = blockIdx.x;
    int a = threadIdx.x;
    int b = bh >> 4, h = bh & 15;
    float run_cv = g_psum_cv[(bh * 32 + ch) * A_ + a];
    float run_c = g_psum_c[bh * 32 + ch];
    const float* cr = g_cross + bh * N_;
    const float* dg = g_diag + bh * N_;
    const float* ex = g_extra + bh * N_;
    const float* pe = g_p2e + h * N_;
    int n0 = ch * 128;
#pragma unroll 4
    for (int i = 0; i < 128; i++) {
        int n = n0 + i;
        float cn = cr[n];
        float dn = dg[n];
        float peE = pe[n] * ex[n];
        size_t vidx = ((size_t)(b * N_ + n) * H_ + h) * A_ + a;
        float v = g_values[vidx];
        run_cv = fmaf(cn, v, run_cv);   // inclusive cumsum
        run_c += cn;
        float num = fmaf(run_cv, peE, v * dn);
        float den = fmaf(run_c, peE, dn);
        g_outbuf[vidx] = num / den;
    }
}

// ---------------------------------------------------------------------------
// Launcher
// ---------------------------------------------------------------------------
extern "C" void kernel_launch(void* const* d_in, const int* in_sizes, int n_in,
                              void* d_out, int out_size) {
    const float* x  = (const float*)d_in[0];
    const float* k1 = (const float*)d_in[1];
    const float* k2 = (const float*)d_in[2];
    const float* k3 = (const float*)d_in[3];
    const float* a1 = (const float*)d_in[4];
    const float* a2 = (const float*)d_in[5];
    const float* b1 = (const float*)d_in[6];
    const float* b2 = (const float*)d_in[7];
    const float* cc = (const float*)d_in[8];
    const float* vw = (const float*)d_in[9];
    const float* ow = (const float*)d_in[10];
    float* out = (float*)d_out;

    // Resolve scratch addresses (pure queries; graph-capture safe)
    void *p_wvt, *p_wot, *p_values, *p_outbuf;
    cudaGetSymbolAddress(&p_wvt, g_wv_t);
    cudaGetSymbolAddress(&p_wot, g_wo_t);
    cudaGetSymbolAddress(&p_values, g_values);
    cudaGetSymbolAddress(&p_outbuf, g_outbuf);

    transpose_weights<<<(1024 * 1024) / 256, 256>>>(vw, ow);
    pos_kernel<<<(H_ * N_) / 256, 256>>>(a1, a2, b1, b2, cc);
    proj_kernel<<<M_, 256>>>(x, k1, k2, k3);

    // values = x @ Wv_t   -> [b,n,h,a]
    sgemm<<<dim3(8, 128), 256>>>(x, (const float*)p_wvt, (float*)p_values);

    scan_partial<<<dim3(32, B_ * H_), A_>>>();
    scan_prefix<<<B_ * H_, A_>>>();
    scan_final<<<dim3(32, B_ * H_), A_>>>();

    // result = outbuf @ Wo_t -> d_out
    sgemm<<<dim3(8, 128), 256>>>((const float*)p_outbuf, (const float*)p_wot, out);
}

// round 3
// speedup vs baseline: 2.1889x; 2.1889x over previous
#include <cuda_runtime.h>
#include <cuda_bf16.h>
#include <math.h>
#include <stdint.h>

// Problem shapes (fixed)
#define B_ 4
#define N_ 4096
#define W_ 1024
#define H_ 16
#define A_ 64
#define HA_ 1024           // H_*A_
#define M_ 16384           // B_*N_

// ---------------------------------------------------------------------------
// Scratch (no allocations allowed -> __device__ globals)
// ---------------------------------------------------------------------------
__device__ float g_values[M_ * HA_];        // [b,n,h,a]  64 MB
__device__ float g_outbuf[M_ * HA_];        // [b,n,h,a]  64 MB
__device__ float g_wv_t[HA_ * W_];          // [n=h*A+a][k=w]  4 MB
__device__ float g_wo_t[W_ * HA_];          // [n=w][k=h*A+a]  4 MB
__device__ float g_cross[B_ * H_ * N_];     // exp'd, [b,h,n]
__device__ float g_diag [B_ * H_ * N_];
__device__ float g_extra[B_ * H_ * N_];
__device__ float g_p1 [H_ * N_];
__device__ float g_p2e[H_ * N_];            // exp'd
__device__ float g_psum_cv[B_ * H_ * 32 * A_];
__device__ float g_psum_c [B_ * H_ * 32];

__device__ __forceinline__ float to_tf32(float x) {
    float r;
    asm("cvt.rna.tf32.f32 %0, %1;" : "=f"(r) : "f"(x));
    return r;
}

// ---------------------------------------------------------------------------
// 1) Weight re-layout (B^T tiles, K-major rows):
//    g_wv_t[(h*64+a)*1024 + w] = vw[h,w,a]    (GEMM1 B: n=h*64+a, k=w)
//    g_wo_t[w*1024 + (h*64+a)] = ow[h,w,a]    (GEMM2 B: n=w,      k=h*64+a)
// ---------------------------------------------------------------------------
__global__ void transpose_weights(const float* __restrict__ vw,
                                  const float* __restrict__ ow) {
    int idx = blockIdx.x * blockDim.x + threadIdx.x;   // 0..1024*1024-1
    {
        int n = idx >> 10;          // h*64+a
        int w = idx & 1023;
        int h = n >> 6;
        int a = n & 63;
        g_wv_t[idx] = vw[(h * W_ + w) * A_ + a];
    }
    {
        int w = idx >> 10;
        int q = idx & 1023;         // h*64+a
        int h = q >> 6;
        int a = q & 63;
        g_wo_t[idx] = ow[(h * W_ + w) * A_ + a];
    }
}

// ---------------------------------------------------------------------------
// 2) Positional
// ---------------------------------------------------------------------------
__global__ void pos_kernel(const float* __restrict__ a1, const float* __restrict__ a2,
                           const float* __restrict__ b1, const float* __restrict__ b2,
                           const float* __restrict__ cc) {
    int idx = blockIdx.x * blockDim.x + threadIdx.x;
    int h = idx >> 12;
    int n = idx & (N_ - 1);
    float nv = (float)n * (1.0f / 4095.0f);
    float s1 = 0.f, s2 = 0.f;
#pragma unroll 8
    for (int p = 0; p < 64; p++) {
        float cp = cc[h * 64 + p];
        s1 += sinf(fmaf(a1[h * 64 + p], nv, b1[h * 64 + p])) * cp;
        s2 += sinf(fmaf(a2[h * 64 + p], nv, b2[h * 64 + p])) * cp;
    }
    g_p1[idx] = s1;
    s2 = fminf(fmaxf(s2, -20.f), 20.f);
    g_p2e[idx] = expf(s2);
}

// ---------------------------------------------------------------------------
// 3) Projections
// ---------------------------------------------------------------------------
__global__ __launch_bounds__(256) void proj_kernel(const float* __restrict__ x,
                                                   const float* __restrict__ k1,
                                                   const float* __restrict__ k2,
                                                   const float* __restrict__ k3) {
    __shared__ float xs[W_];
    int row = blockIdx.x;
    const float4* xr = (const float4*)(x + (size_t)row * W_);
    float4* xs4 = (float4*)xs;
    xs4[threadIdx.x] = xr[threadIdx.x];
    __syncthreads();

    int warp = threadIdx.x >> 5;
    int lane = threadIdx.x & 31;
    int b = row >> 12;
    int n = row & (N_ - 1);

    for (int j = warp; j < 48; j += 8) {
        int which = j >> 4;
        int h = j & 15;
        const float* kk = (which == 0) ? k1 : ((which == 1) ? k2 : k3);
        const float* kh = kk + h * W_;
        float s = 0.f;
#pragma unroll 8
        for (int i = lane; i < W_; i += 32) s += xs[i] * kh[i];
#pragma unroll
        for (int o = 16; o; o >>= 1) s += __shfl_xor_sync(0xffffffffu, s, o);
        if (lane == 0) {
            if (which == 0) s += g_p1[h * N_ + n];
            s = fminf(fmaxf(s, -20.f), 20.f);
            s = expf(s);
            int off = (b * H_ + h) * N_ + n;
            if (which == 0)      g_cross[off] = s;
            else if (which == 1) g_diag[off]  = s;
            else                 g_extra[off] = s;
        }
    }
}

// ---------------------------------------------------------------------------
// 4/7) tf32 mma.sync GEMM: C[M,1024] = A[M,1024] @ Bt[1024,1024]^T
//      (Bt stored [n][k] row-major = B col-major).
//      CTA 128x128, BK=16, 8 warps (2x4), warp tile 64x32.
// ---------------------------------------------------------------------------
#define BK 16
#define KPAD 20                // 16 + 4 pad floats per row
#define KT2 (1024 / BK)        // 64 k-tiles

__device__ __forceinline__ void mma1688(float* c, const uint32_t* a, const uint32_t* b) {
    asm volatile(
        "mma.sync.aligned.m16n8k8.row.col.f32.tf32.tf32.f32 "
        "{%0,%1,%2,%3}, {%4,%5,%6,%7}, {%8,%9}, {%0,%1,%2,%3};"
        : "+f"(c[0]), "+f"(c[1]), "+f"(c[2]), "+f"(c[3])
        : "r"(a[0]), "r"(a[1]), "r"(a[2]), "r"(a[3]), "r"(b[0]), "r"(b[1]));
}

__global__ __launch_bounds__(256) void gemm_tf32(const float* __restrict__ A,
                                                 const float* __restrict__ Bt,
                                                 float* __restrict__ C) {
    __shared__ float As[2][128 * KPAD];
    __shared__ float Bs[2][128 * KPAD];

    int tid = threadIdx.x;
    int lane = tid & 31, wid = tid >> 5;
    int wm = wid >> 2;            // 0..1  (64-row slab)
    int wn = wid & 3;             // 0..3  (32-col slab)
    int gid = lane >> 2;          // 0..7
    int tig = lane & 3;           // 0..3

    int bn = blockIdx.x, bm = blockIdx.y;
    const float* Ag = A + (size_t)(bm * 128) * 1024;
    const float* Bg = Bt + (size_t)(bn * 128) * 1024;

    // global-load addressing: 2 float4 per thread per matrix per tile
    int lrow = tid >> 2;          // 0..63 (+64 for second)
    int lk4 = (tid & 3) * 4;      // 0,4,8,12

    float c[4][4][4];
#pragma unroll
    for (int i = 0; i < 4; i++)
#pragma unroll
        for (int j = 0; j < 4; j++)
#pragma unroll
            for (int q = 0; q < 4; q++) c[i][j][q] = 0.f;

    float4 pa[2], pb[2];

    auto g_load = [&](int t) {
        int k0 = t * BK;
#pragma unroll
        for (int i = 0; i < 2; i++) {
            pa[i] = *(const float4*)(Ag + (size_t)(lrow + i * 64) * 1024 + k0 + lk4);
            pb[i] = *(const float4*)(Bg + (size_t)(lrow + i * 64) * 1024 + k0 + lk4);
        }
    };
    auto s_store = [&](int buf) {
#pragma unroll
        for (int i = 0; i < 2; i++) {
            float4 va = pa[i], vb = pb[i];
            va.x = to_tf32(va.x); va.y = to_tf32(va.y);
            va.z = to_tf32(va.z); va.w = to_tf32(va.w);
            vb.x = to_tf32(vb.x); vb.y = to_tf32(vb.y);
            vb.z = to_tf32(vb.z); vb.w = to_tf32(vb.w);
            *(float4*)(&As[buf][(lrow + i * 64) * KPAD + lk4]) = va;
            *(float4*)(&Bs[buf][(lrow + i * 64) * KPAD + lk4]) = vb;
        }
    };

    g_load(0);
    s_store(0);
    __syncthreads();

    for (int t = 0; t < KT2; t++) {
        int buf = t & 1;
        if (t + 1 < KT2) g_load(t + 1);

        const float* as = As[buf];
        const float* bs = Bs[buf];
#pragma unroll
        for (int kk = 0; kk < BK; kk += 8) {
            uint32_t af[4][4], bf[4][2];
#pragma unroll
            for (int mt = 0; mt < 4; mt++) {
                int m = wm * 64 + mt * 16;
                af[mt][0] = __float_as_uint(as[(m + gid) * KPAD + kk + tig]);
                af[mt][1] = __float_as_uint(as[(m + gid + 8) * KPAD + kk + tig]);
                af[mt][2] = __float_as_uint(as[(m + gid) * KPAD + kk + tig + 4]);
                af[mt][3] = __float_as_uint(as[(m + gid + 8) * KPAD + kk + tig + 4]);
            }
#pragma unroll
            for (int nt = 0; nt < 4; nt++) {
                int n = wn * 32 + nt * 8;
                bf[nt][0] = __float_as_uint(bs[(n + gid) * KPAD + kk + tig]);
                bf[nt][1] = __float_as_uint(bs[(n + gid) * KPAD + kk + tig + 4]);
            }
#pragma unroll
            for (int mt = 0; mt < 4; mt++)
#pragma unroll
                for (int nt = 0; nt < 4; nt++)
                    mma1688(c[mt][nt], af[mt], bf[nt]);
        }

        __syncthreads();
        if (t + 1 < KT2) {
            s_store((t + 1) & 1);
            __syncthreads();
        }
    }

    // epilogue
#pragma unroll
    for (int mt = 0; mt < 4; mt++) {
        int r0 = bm * 128 + wm * 64 + mt * 16 + gid;
#pragma unroll
        for (int nt = 0; nt < 4; nt++) {
            int col = bn * 128 + wn * 32 + nt * 8 + tig * 2;
            *(float2*)(&C[(size_t)r0 * 1024 + col]) = make_float2(c[mt][nt][0], c[mt][nt][1]);
            *(float2*)(&C[(size_t)(r0 + 8) * 1024 + col]) = make_float2(c[mt][nt][2], c[mt][nt][3]);
        }
    }
}

// ---------------------------------------------------------------------------
// 5) Scan phase 1
// ---------------------------------------------------------------------------
__global__ void scan_partial() {
    int bh = blockIdx.y;
    int ch = blockIdx.x;
    int a = threadIdx.x;
    int b = bh >> 4, h = bh & 15;
    const float* cr = g_cross + bh * N_;
    int n0 = ch * 128;
    float sc = 0.f, scv = 0.f;
#pragma unroll 4
    for (int i = 0; i < 128; i++) {
        int n = n0 + i;
        float cn = cr[n];
        float v = g_values[((size_t)(b * N_ + n) * H_ + h) * A_ + a];
        sc += cn;
        scv = fmaf(cn, v, scv);
    }
    g_psum_cv[(bh * 32 + ch) * A_ + a] = scv;
    if (a == 0) g_psum_c[bh * 32 + ch] = sc;
}

// ---------------------------------------------------------------------------
// 6) Scan phase 2
// ---------------------------------------------------------------------------
__global__ void scan_prefix() {
    int bh = blockIdx.x;
    int a = threadIdx.x;
    float run = 0.f;
    for (int ch = 0; ch < 32; ch++) {
        int idx = (bh * 32 + ch) * A_ + a;
        float v = g_psum_cv[idx];
        g_psum_cv[idx] = run;
        run += v;
    }
    if (a == 0) {
        float rc = 0.f;
        for (int ch = 0; ch < 32; ch++) {
            float v = g_psum_c[bh * 32 + ch];
            g_psum_c[bh * 32 + ch] = rc;
            rc += v;
        }
    }
}

// ---------------------------------------------------------------------------
// 7) Scan phase 3
// ---------------------------------------------------------------------------
__global__ void scan_final() {
    int bh = blockIdx.y;
    int ch = blockIdx.x;
    int a = threadIdx.x;
    int b = bh >> 4, h = bh & 15;
    float run_cv = g_psum_cv[(bh * 32 + ch) * A_ + a];
    float run_c = g_psum_c[bh * 32 + ch];
    const float* cr = g_cross + bh * N_;
    const float* dg = g_diag + bh * N_;
    const float* ex = g_extra + bh * N_;
    const float* pe = g_p2e + h * N_;
    int n0 = ch * 128;
#pragma unroll 4
    for (int i = 0; i < 128; i++) {
        int n = n0 + i;
        float cn = cr[n];
        float dn = dg[n];
        float peE = pe[n] * ex[n];
        size_t vidx = ((size_t)(b * N_ + n) * H_ + h) * A_ + a;
        float v = g_values[vidx];
        run_cv = fmaf(cn, v, run_cv);
        run_c += cn;
        float num = fmaf(run_cv, peE, v * dn);
        float den = fmaf(run_c, peE, dn);
        g_outbuf[vidx] = num / den;
    }
}

// ---------------------------------------------------------------------------
// Launcher
// ---------------------------------------------------------------------------
extern "C" void kernel_launch(void* const* d_in, const int* in_sizes, int n_in,
                              void* d_out, int out_size) {
    const float* x  = (const float*)d_in[0];
    const float* k1 = (const float*)d_in[1];
    const float* k2 = (const float*)d_in[2];
    const float* k3 = (const float*)d_in[3];
    const float* a1 = (const float*)d_in[4];
    const float* a2 = (const float*)d_in[5];
    const float* b1 = (const float*)d_in[6];
    const float* b2 = (const float*)d_in[7];
    const float* cc = (const float*)d_in[8];
    const float* vw = (const float*)d_in[9];
    const float* ow = (const float*)d_in[10];
    float* out = (float*)d_out;

    void *p_wvt, *p_wot, *p_values, *p_outbuf;
    cudaGetSymbolAddress(&p_wvt, g_wv_t);
    cudaGetSymbolAddress(&p_wot, g_wo_t);
    cudaGetSymbolAddress(&p_values, g_values);
    cudaGetSymbolAddress(&p_outbuf, g_outbuf);

    transpose_weights<<<(1024 * 1024) / 256, 256>>>(vw, ow);
    pos_kernel<<<(H_ * N_) / 256, 256>>>(a1, a2, b1, b2, cc);
    proj_kernel<<<M_, 256>>>(x, k1, k2, k3);

    // values = x @ Wv^T  -> [b,n,h,a]
    gemm_tf32<<<dim3(8, 128), 256>>>(x, (const float*)p_wvt, (float*)p_values);

    scan_partial<<<dim3(32, B_ * H_), A_>>>();
    scan_prefix<<<B_ * H_, A_>>>();
    scan_final<<<dim3(32, B_ * H_), A_>>>();

    // result = outbuf @ Wo^T -> d_out
    gemm_tf32<<<dim3(8, 128), 256>>>((const float*)p_outbuf, (const float*)p_wot, out);
}

// round 4
// speedup vs baseline: 2.4369x; 1.1133x over previous
#include <cuda_runtime.h>
#include <cuda_bf16.h>
#include <math.h>
#include <stdint.h>

// Problem shapes (fixed)
#define B_ 4
#define N_ 4096
#define W_ 1024
#define H_ 16
#define A_ 64
#define HA_ 1024           // H_*A_
#define M_ 16384           // B_*N_

// ---------------------------------------------------------------------------
// Scratch (no allocations allowed -> __device__ globals)
// ---------------------------------------------------------------------------
__device__ float g_values[M_ * HA_];        // [b,n,h,a]  64 MB
__device__ float g_outbuf[M_ * HA_];        // [b,n,h,a]  64 MB (tf32-rounded)
__device__ float g_xr[M_ * W_];             // tf32-rounded x, 64 MB
__device__ float g_wv_t[HA_ * W_];          // [n=h*A+a][k=w]  4 MB (tf32-rounded)
__device__ float g_wo_t[W_ * HA_];          // [n=w][k=h*A+a]  4 MB (tf32-rounded)
__device__ float g_cross[B_ * H_ * N_];     // exp'd, [b,h,n]
__device__ float g_diag [B_ * H_ * N_];
__device__ float g_extra[B_ * H_ * N_];
__device__ float g_p1 [H_ * N_];
__device__ float g_p2e[H_ * N_];            // exp'd
__device__ float g_psum_cv[B_ * H_ * 32 * A_];
__device__ float g_psum_c [B_ * H_ * 32];

__device__ __forceinline__ float to_tf32(float x) {
    float r;
    asm("cvt.rna.tf32.f32 %0, %1;" : "=f"(r) : "f"(x));
    return r;
}
__device__ __forceinline__ uint32_t s2u(const void* p) {
    uint32_t r;
    asm("{ .reg .u64 t; cvta.to.shared.u64 t, %1; cvt.u32.u64 %0, t; }" : "=r"(r) : "l"(p));
    return r;
}
__device__ __forceinline__ void cp16(uint32_t dst, const void* src) {
    asm volatile("cp.async.cg.shared.global [%0], [%1], 16;" :: "r"(dst), "l"(src));
}
#define CP_COMMIT() asm volatile("cp.async.commit_group;" ::: "memory")
#define CP_WAIT(n)  asm volatile("cp.async.wait_group %0;" :: "n"(n) : "memory")

// ---------------------------------------------------------------------------
// 1) Weight re-layout (tf32-rounded at rest):
//    g_wv_t[(h*64+a)*1024 + w] = vw[h,w,a]
//    g_wo_t[w*1024 + (h*64+a)] = ow[h,w,a]
// ---------------------------------------------------------------------------
__global__ void transpose_weights(const float* __restrict__ vw,
                                  const float* __restrict__ ow) {
    int idx = blockIdx.x * blockDim.x + threadIdx.x;
    {
        int n = idx >> 10;
        int w = idx & 1023;
        int h = n >> 6;
        int a = n & 63;
        g_wv_t[idx] = to_tf32(vw[(h * W_ + w) * A_ + a]);
    }
    {
        int w = idx >> 10;
        int q = idx & 1023;
        int h = q >> 6;
        int a = q & 63;
        g_wo_t[idx] = to_tf32(ow[(h * W_ + w) * A_ + a]);
    }
}

// ---------------------------------------------------------------------------
// 2) Positional
// ---------------------------------------------------------------------------
__global__ void pos_kernel(const float* __restrict__ a1, const float* __restrict__ a2,
                           const float* __restrict__ b1, const float* __restrict__ b2,
                           const float* __restrict__ cc) {
    int idx = blockIdx.x * blockDim.x + threadIdx.x;
    int h = idx >> 12;
    int n = idx & (N_ - 1);
    float nv = (float)n * (1.0f / 4095.0f);
    float s1 = 0.f, s2 = 0.f;
#pragma unroll 8
    for (int p = 0; p < 64; p++) {
        float cp = cc[h * 64 + p];
        s1 += sinf(fmaf(a1[h * 64 + p], nv, b1[h * 64 + p])) * cp;
        s2 += sinf(fmaf(a2[h * 64 + p], nv, b2[h * 64 + p])) * cp;
    }
    g_p1[idx] = s1;
    s2 = fminf(fmaxf(s2, -20.f), 20.f);
    g_p2e[idx] = expf(s2);
}

// ---------------------------------------------------------------------------
// 3) Projections (+ writes tf32-rounded x copy for GEMM1)
// ---------------------------------------------------------------------------
__global__ __launch_bounds__(256) void proj_kernel(const float* __restrict__ x,
                                                   const float* __restrict__ k1,
                                                   const float* __restrict__ k2,
                                                   const float* __restrict__ k3) {
    __shared__ float xs[W_];
    int row = blockIdx.x;
    const float4* xr = (const float4*)(x + (size_t)row * W_);
    float4* xs4 = (float4*)xs;
    float4 v = xr[threadIdx.x];
    xs4[threadIdx.x] = v;
    // rounded copy for the tensor-core GEMM
    v.x = to_tf32(v.x); v.y = to_tf32(v.y); v.z = to_tf32(v.z); v.w = to_tf32(v.w);
    *(float4*)(g_xr + (size_t)row * W_ + threadIdx.x * 4) = v;
    __syncthreads();

    int warp = threadIdx.x >> 5;
    int lane = threadIdx.x & 31;
    int b = row >> 12;
    int n = row & (N_ - 1);

    for (int j = warp; j < 48; j += 8) {
        int which = j >> 4;
        int h = j & 15;
        const float* kk = (which == 0) ? k1 : ((which == 1) ? k2 : k3);
        const float* kh = kk + h * W_;
        float s = 0.f;
#pragma unroll 8
        for (int i = lane; i < W_; i += 32) s += xs[i] * kh[i];
#pragma unroll
        for (int o = 16; o; o >>= 1) s += __shfl_xor_sync(0xffffffffu, s, o);
        if (lane == 0) {
            if (which == 0) s += g_p1[h * N_ + n];
            s = fminf(fmaxf(s, -20.f), 20.f);
            s = expf(s);
            int off = (b * H_ + h) * N_ + n;
            if (which == 0)      g_cross[off] = s;
            else if (which == 1) g_diag[off]  = s;
            else                 g_extra[off] = s;
        }
    }
}

// ---------------------------------------------------------------------------
// 4/7) tf32 mma.sync GEMM, cp.async 4-stage pipeline.
//      C[M,1024] = A[M,1024] @ Bt[1024,1024]^T  (Bt stored [n][k] row-major).
//      CTA 128x128, BK=16, 8 warps (2x4), warp tile 64x32. Inputs pre-rounded.
// ---------------------------------------------------------------------------
#define BK 16
#define KPAD 20                      // floats per smem row (80 B, 16B-aligned)
#define KT2 (1024 / BK)              // 64 k-tiles
#define STG 4
#define HALF_BYTES (128 * KPAD * 4)  // one matrix tile: 10240 B
#define STAGE_BYTES (2 * HALF_BYTES) // 20480 B
#define GSMEM (STG * STAGE_BYTES)    // 81920 B

__device__ __forceinline__ void mma1688(float* c, const uint32_t* a, const uint32_t* b) {
    asm volatile(
        "mma.sync.aligned.m16n8k8.row.col.f32.tf32.tf32.f32 "
        "{%0,%1,%2,%3}, {%4,%5,%6,%7}, {%8,%9}, {%0,%1,%2,%3};"
        : "+f"(c[0]), "+f"(c[1]), "+f"(c[2]), "+f"(c[3])
        : "r"(a[0]), "r"(a[1]), "r"(a[2]), "r"(a[3]), "r"(b[0]), "r"(b[1]));
}

__global__ __launch_bounds__(256, 2) void gemm_tf32(const float* __restrict__ A,
                                                    const float* __restrict__ Bt,
                                                    float* __restrict__ C) {
    extern __shared__ __align__(16) float smem[];
    uint32_t smem_u = s2u(smem);

    int tid = threadIdx.x;
    int lane = tid & 31, wid = tid >> 5;
    int wm = wid >> 2;            // 0..1
    int wn = wid & 3;             // 0..3
    int gid = lane >> 2;          // 0..7
    int tig = lane & 3;           // 0..3

    int bn = blockIdx.x, bm = blockIdx.y;
    const float* Ag = A + (size_t)(bm * 128) * 1024;
    const float* Bg = Bt + (size_t)(bn * 128) * 1024;

    // per-thread copy addressing: 2 chunks per matrix per tile
    int c0row = tid >> 2;         // 0..63
    int c0k4 = (tid & 3);         // 0..3 (16B chunk within 64B row)

    float c[4][4][4];
#pragma unroll
    for (int i = 0; i < 4; i++)
#pragma unroll
        for (int j = 0; j < 4; j++)
#pragma unroll
            for (int q = 0; q < 4; q++) c[i][j][q] = 0.f;

    auto load_stage = [&](int t, int s) {
        int k0 = t * BK;
        uint32_t base = smem_u + s * STAGE_BYTES;
#pragma unroll
        for (int i = 0; i < 2; i++) {
            int row = c0row + i * 64;
            uint32_t off = (uint32_t)(row * (KPAD * 4) + c0k4 * 16);
            cp16(base + off, Ag + (size_t)row * 1024 + k0 + c0k4 * 4);
            cp16(base + HALF_BYTES + off, Bg + (size_t)row * 1024 + k0 + c0k4 * 4);
        }
    };

#pragma unroll
    for (int s = 0; s < STG - 1; s++) {
        load_stage(s, s);
        CP_COMMIT();
    }

    int buf = 0;
    for (int t = 0; t < KT2; t++) {
        CP_WAIT(STG - 2);
        __syncthreads();
        if (t + STG - 1 < KT2) {
            int nb = buf + (STG - 1);
            if (nb >= STG) nb -= STG;
            load_stage(t + STG - 1, nb);
            CP_COMMIT();
        } else {
            CP_COMMIT();   // keep group count balanced for the wait above
        }

        const float* as = smem + (size_t)buf * (STAGE_BYTES / 4);
        const float* bs = as + (HALF_BYTES / 4);
        const float* ap = as + (wm * 64 + gid) * KPAD + tig;
        const float* bp = bs + (wn * 32 + gid) * KPAD + tig;
#pragma unroll
        for (int kk = 0; kk < BK; kk += 8) {
            uint32_t af[4][4], bf[4][2];
#pragma unroll
            for (int mt = 0; mt < 4; mt++) {
                af[mt][0] = __float_as_uint(ap[mt * 16 * KPAD + kk]);
                af[mt][1] = __float_as_uint(ap[(mt * 16 + 8) * KPAD + kk]);
                af[mt][2] = __float_as_uint(ap[mt * 16 * KPAD + kk + 4]);
                af[mt][3] = __float_as_uint(ap[(mt * 16 + 8) * KPAD + kk + 4]);
            }
#pragma unroll
            for (int nt = 0; nt < 4; nt++) {
                bf[nt][0] = __float_as_uint(bp[nt * 8 * KPAD + kk]);
                bf[nt][1] = __float_as_uint(bp[nt * 8 * KPAD + kk + 4]);
            }
#pragma unroll
            for (int mt = 0; mt < 4; mt++)
#pragma unroll
                for (int nt = 0; nt < 4; nt++)
                    mma1688(c[mt][nt], af[mt], bf[nt]);
        }
        buf = (buf + 1 == STG) ? 0 : buf + 1;
    }

    // epilogue
#pragma unroll
    for (int mt = 0; mt < 4; mt++) {
        int r0 = bm * 128 + wm * 64 + mt * 16 + gid;
#pragma unroll
        for (int nt = 0; nt < 4; nt++) {
            int col = bn * 128 + wn * 32 + nt * 8 + tig * 2;
            *(float2*)(&C[(size_t)r0 * 1024 + col]) = make_float2(c[mt][nt][0], c[mt][nt][1]);
            *(float2*)(&C[(size_t)(r0 + 8) * 1024 + col]) = make_float2(c[mt][nt][2], c[mt][nt][3]);
        }
    }
}

// ---------------------------------------------------------------------------
// 5) Scan phase 1
// ---------------------------------------------------------------------------
__global__ void scan_partial() {
    int bh = blockIdx.y;
    int ch = blockIdx.x;
    int a = threadIdx.x;
    int b = bh >> 4, h = bh & 15;
    const float* cr = g_cross + bh * N_;
    int n0 = ch * 128;
    float sc = 0.f, scv = 0.f;
#pragma unroll 4
    for (int i = 0; i < 128; i++) {
        int n = n0 + i;
        float cn = cr[n];
        float v = g_values[((size_t)(b * N_ + n) * H_ + h) * A_ + a];
        sc += cn;
        scv = fmaf(cn, v, scv);
    }
    g_psum_cv[(bh * 32 + ch) * A_ + a] = scv;
    if (a == 0) g_psum_c[bh * 32 + ch] = sc;
}

// ---------------------------------------------------------------------------
// 6) Scan phase 2
// ---------------------------------------------------------------------------
__global__ void scan_prefix() {
    int bh = blockIdx.x;
    int a = threadIdx.x;
    float run = 0.f;
    for (int ch = 0; ch < 32; ch++) {
        int idx = (bh * 32 + ch) * A_ + a;
        float v = g_psum_cv[idx];
        g_psum_cv[idx] = run;
        run += v;
    }
    if (a == 0) {
        float rc = 0.f;
        for (int ch = 0; ch < 32; ch++) {
            float v = g_psum_c[bh * 32 + ch];
            g_psum_c[bh * 32 + ch] = rc;
            rc += v;
        }
    }
}

// ---------------------------------------------------------------------------
// 7) Scan phase 3 (stores tf32-rounded for GEMM2)
// ---------------------------------------------------------------------------
__global__ void scan_final() {
    int bh = blockIdx.y;
    int ch = blockIdx.x;
    int a = threadIdx.x;
    int b = bh >> 4, h = bh & 15;
    float run_cv = g_psum_cv[(bh * 32 + ch) * A_ + a];
    float run_c = g_psum_c[bh * 32 + ch];
    const float* cr = g_cross + bh * N_;
    const float* dg = g_diag + bh * N_;
    const float* ex = g_extra + bh * N_;
    const float* pe = g_p2e + h * N_;
    int n0 = ch * 128;
#pragma unroll 4
    for (int i = 0; i < 128; i++) {
        int n = n0 + i;
        float cn = cr[n];
        float dn = dg[n];
        float peE = pe[n] * ex[n];
        size_t vidx = ((size_t)(b * N_ + n) * H_ + h) * A_ + a;
        float v = g_values[vidx];
        run_cv = fmaf(cn, v, run_cv);
        run_c += cn;
        float num = fmaf(run_cv, peE, v * dn);
        float den = fmaf(run_c, peE, dn);
        g_outbuf[vidx] = to_tf32(num / den);
    }
}

// ---------------------------------------------------------------------------
// Launcher
// ---------------------------------------------------------------------------
extern "C" void kernel_launch(void* const* d_in, const int* in_sizes, int n_in,
                              void* d_out, int out_size) {
    const float* x  = (const float*)d_in[0];
    const float* k1 = (const float*)d_in[1];
    const float* k2 = (const float*)d_in[2];
    const float* k3 = (const float*)d_in[3];
    const float* a1 = (const float*)d_in[4];
    const float* a2 = (const float*)d_in[5];
    const float* b1 = (const float*)d_in[6];
    const float* b2 = (const float*)d_in[7];
    const float* cc = (const float*)d_in[8];
    const float* vw = (const float*)d_in[9];
    const float* ow = (const float*)d_in[10];
    float* out = (float*)d_out;

    void *p_wvt, *p_wot, *p_values, *p_outbuf, *p_xr;
    cudaGetSymbolAddress(&p_wvt, g_wv_t);
    cudaGetSymbolAddress(&p_wot, g_wo_t);
    cudaGetSymbolAddress(&p_values, g_values);
    cudaGetSymbolAddress(&p_outbuf, g_outbuf);
    cudaGetSymbolAddress(&p_xr, g_xr);

    cudaFuncSetAttribute(gemm_tf32, cudaFuncAttributeMaxDynamicSharedMemorySize, GSMEM);

    transpose_weights<<<(1024 * 1024) / 256, 256>>>(vw, ow);
    pos_kernel<<<(H_ * N_) / 256, 256>>>(a1, a2, b1, b2, cc);
    proj_kernel<<<M_, 256>>>(x, k1, k2, k3);

    // values = x @ Wv^T  -> [b,n,h,a]
    gemm_tf32<<<dim3(8, 128), 256, GSMEM>>>((const float*)p_xr, (const float*)p_wvt,
                                            (float*)p_values);

    scan_partial<<<dim3(32, B_ * H_), A_>>>();
    scan_prefix<<<B_ * H_, A_>>>();
    scan_final<<<dim3(32, B_ * H_), A_>>>();

    // result = outbuf @ Wo^T -> d_out
    gemm_tf32<<<dim3(8, 128), 256, GSMEM>>>((const float*)p_outbuf,
                                            (const float*)p_wot, out);
}

// round 5
// speedup vs baseline: 3.5003x; 1.4364x over previous
#include <cuda_runtime.h>
#include <cuda_fp16.h>
#include <math.h>
#include <stdint.h>

// Problem shapes (fixed)
#define B_ 4
#define N_ 4096
#define W_ 1024
#define H_ 16
#define A_ 64
#define HA_ 1024           // H_*A_
#define M_ 16384           // B_*N_

// ---------------------------------------------------------------------------
// Scratch (no allocations allowed -> __device__ globals)
// ---------------------------------------------------------------------------
__device__ float  g_values[M_ * HA_];       // [b,n,h,a]  64 MB (GEMM1 out, f32)
__device__ __half g_outh[M_ * HA_];         // [b,n,h,a]  32 MB (GEMM2 in, fp16)
__device__ __half g_xh[M_ * W_];            // fp16 x, 32 MB
__device__ __half g_wv_h[HA_ * W_];         // [n=h*A+a][k=w]  2 MB
__device__ __half g_wo_h[W_ * HA_];         // [n=w][k=h*A+a]  2 MB
__device__ float g_cross[B_ * H_ * N_];     // exp'd, [b,h,n]
__device__ float g_diag [B_ * H_ * N_];
__device__ float g_extra[B_ * H_ * N_];
__device__ float g_p1 [H_ * N_];
__device__ float g_p2e[H_ * N_];            // exp'd
__device__ float g_psum_cv[B_ * H_ * 32 * A_];
__device__ float g_psum_c [B_ * H_ * 32];

__device__ __forceinline__ uint32_t s2u(const void* p) {
    uint32_t r;
    asm("{ .reg .u64 t; cvta.to.shared.u64 t, %1; cvt.u32.u64 %0, t; }" : "=r"(r) : "l"(p));
    return r;
}
__device__ __forceinline__ void cp16(uint32_t dst, const void* src) {
    asm volatile("cp.async.cg.shared.global [%0], [%1], 16;" :: "r"(dst), "l"(src));
}
#define CP_COMMIT() asm volatile("cp.async.commit_group;" ::: "memory")
#define CP_WAIT(n)  asm volatile("cp.async.wait_group %0;" :: "n"(n) : "memory")

// ---------------------------------------------------------------------------
// 1) Weight re-layout (fp16 at rest):
//    g_wv_h[(h*64+a)*1024 + w] = vw[h,w,a]
//    g_wo_h[w*1024 + (h*64+a)] = ow[h,w,a]
// ---------------------------------------------------------------------------
__global__ void transpose_weights(const float* __restrict__ vw,
                                  const float* __restrict__ ow) {
    int idx = blockIdx.x * blockDim.x + threadIdx.x;
    {
        int n = idx >> 10;
        int w = idx & 1023;
        int h = n >> 6;
        int a = n & 63;
        g_wv_h[idx] = __float2half_rn(vw[(h * W_ + w) * A_ + a]);
    }
    {
        int w = idx >> 10;
        int q = idx & 1023;
        int h = q >> 6;
        int a = q & 63;
        g_wo_h[idx] = __float2half_rn(ow[(h * W_ + w) * A_ + a]);
    }
}

// ---------------------------------------------------------------------------
// 2) Positional
// ---------------------------------------------------------------------------
__global__ void pos_kernel(const float* __restrict__ a1, const float* __restrict__ a2,
                           const float* __restrict__ b1, const float* __restrict__ b2,
                           const float* __restrict__ cc) {
    int idx = blockIdx.x * blockDim.x + threadIdx.x;
    int h = idx >> 12;
    int n = idx & (N_ - 1);
    float nv = (float)n * (1.0f / 4095.0f);
    float s1 = 0.f, s2 = 0.f;
#pragma unroll 8
    for (int p = 0; p < 64; p++) {
        float cp = cc[h * 64 + p];
        s1 += sinf(fmaf(a1[h * 64 + p], nv, b1[h * 64 + p])) * cp;
        s2 += sinf(fmaf(a2[h * 64 + p], nv, b2[h * 64 + p])) * cp;
    }
    g_p1[idx] = s1;
    s2 = fminf(fmaxf(s2, -20.f), 20.f);
    g_p2e[idx] = expf(s2);
}

// ---------------------------------------------------------------------------
// 3) Projections (+ writes fp16 x copy for GEMM1)
// ---------------------------------------------------------------------------
__global__ __launch_bounds__(256) void proj_kernel(const float* __restrict__ x,
                                                   const float* __restrict__ k1,
                                                   const float* __restrict__ k2,
                                                   const float* __restrict__ k3) {
    __shared__ float xs[W_];
    int row = blockIdx.x;
    const float4* xr = (const float4*)(x + (size_t)row * W_);
    float4* xs4 = (float4*)xs;
    float4 v = xr[threadIdx.x];
    xs4[threadIdx.x] = v;
    // fp16 copy for the tensor-core GEMM
    __half2 h0 = __floats2half2_rn(v.x, v.y);
    __half2 h1 = __floats2half2_rn(v.z, v.w);
    *(uint2*)(g_xh + (size_t)row * W_ + threadIdx.x * 4) =
        make_uint2(*(uint32_t*)&h0, *(uint32_t*)&h1);
    __syncthreads();

    int warp = threadIdx.x >> 5;
    int lane = threadIdx.x & 31;
    int b = row >> 12;
    int n = row & (N_ - 1);

    for (int j = warp; j < 48; j += 8) {
        int which = j >> 4;
        int h = j & 15;
        const float* kk = (which == 0) ? k1 : ((which == 1) ? k2 : k3);
        const float* kh = kk + h * W_;
        float s = 0.f;
#pragma unroll 8
        for (int i = lane; i < W_; i += 32) s += xs[i] * kh[i];
#pragma unroll
        for (int o = 16; o; o >>= 1) s += __shfl_xor_sync(0xffffffffu, s, o);
        if (lane == 0) {
            if (which == 0) s += g_p1[h * N_ + n];
            s = fminf(fmaxf(s, -20.f), 20.f);
            s = expf(s);
            int off = (b * H_ + h) * N_ + n;
            if (which == 0)      g_cross[off] = s;
            else if (which == 1) g_diag[off]  = s;
            else                 g_extra[off] = s;
        }
    }
}

// ---------------------------------------------------------------------------
// 4/7) fp16 mma.m16n8k16 GEMM, cp.async 4-stage pipeline, ldmatrix fragments.
//      C[M,1024] = A[M,1024] @ Bt[1024,1024]^T  (Bt stored [n][k] row-major).
//      CTA 128x128, BK=32, 8 warps (2x4), warp tile 64x32.
// ---------------------------------------------------------------------------
#define BK 32
#define KPADH 40                       // halves per smem row (80 B)
#define KT2 (1024 / BK)                // 32 k-tiles
#define STG 4
#define HALF_BYTES (128 * KPADH * 2)   // one matrix tile: 10240 B
#define STAGE_BYTES (2 * HALF_BYTES)   // 20480 B
#define GSMEM (STG * STAGE_BYTES)      // 81920 B

__device__ __forceinline__ void mma16816(float* c, const uint32_t* a, const uint32_t* b) {
    asm volatile(
        "mma.sync.aligned.m16n8k16.row.col.f32.f16.f16.f32 "
        "{%0,%1,%2,%3}, {%4,%5,%6,%7}, {%8,%9}, {%0,%1,%2,%3};"
        : "+f"(c[0]), "+f"(c[1]), "+f"(c[2]), "+f"(c[3])
        : "r"(a[0]), "r"(a[1]), "r"(a[2]), "r"(a[3]), "r"(b[0]), "r"(b[1]));
}
__device__ __forceinline__ void ldsm4(uint32_t* r, uint32_t addr) {
    asm volatile("ldmatrix.sync.aligned.m8n8.x4.shared.b16 {%0,%1,%2,%3}, [%4];"
                 : "=r"(r[0]), "=r"(r[1]), "=r"(r[2]), "=r"(r[3]) : "r"(addr));
}

__global__ __launch_bounds__(256, 2) void gemm_f16(const __half* __restrict__ A,
                                                   const __half* __restrict__ Bt,
                                                   float* __restrict__ C) {
    extern __shared__ __align__(16) char smem[];
    uint32_t smem_u = s2u(smem);

    int tid = threadIdx.x;
    int lane = tid & 31, wid = tid >> 5;
    int wm = wid >> 2;            // 0..1
    int wn = wid & 3;             // 0..3
    int gid = lane >> 2;          // 0..7
    int tig = lane & 3;           // 0..3
    int lr = lane & 15;           // ldmatrix row within 16
    int lk = (lane >> 4) << 3;    // 0 or 8 (k-halves offset)

    int bn = blockIdx.x, bm = blockIdx.y;
    const __half* Ag = A + (size_t)(bm * 128) * 1024;
    const __half* Bg = Bt + (size_t)(bn * 128) * 1024;

    // per-thread copy addressing: row 64B = 4 x 16B chunks
    int c0row = tid >> 2;         // 0..63  (+64 for second half)
    int c0k = (tid & 3) * 8;      // half-offset of 16B chunk within 32-halves row

    float c[4][4][4];
#pragma unroll
    for (int i = 0; i < 4; i++)
#pragma unroll
        for (int j = 0; j < 4; j++)
#pragma unroll
            for (int q = 0; q < 4; q++) c[i][j][q] = 0.f;

    auto load_stage = [&](int t, int s) {
        int k0 = t * BK;
        uint32_t base = smem_u + s * STAGE_BYTES;
#pragma unroll
        for (int i = 0; i < 2; i++) {
            int row = c0row + i * 64;
            uint32_t off = (uint32_t)(row * (KPADH * 2) + c0k * 2);
            cp16(base + off, Ag + (size_t)row * 1024 + k0 + c0k);
            cp16(base + HALF_BYTES + off, Bg + (size_t)row * 1024 + k0 + c0k);
        }
    };

#pragma unroll
    for (int s = 0; s < STG - 1; s++) {
        load_stage(s, s);
        CP_COMMIT();
    }

    int buf = 0;
    for (int t = 0; t < KT2; t++) {
        CP_WAIT(STG - 2);
        __syncthreads();
        if (t + STG - 1 < KT2) {
            int nb = buf + (STG - 1);
            if (nb >= STG) nb -= STG;
            load_stage(t + STG - 1, nb);
            CP_COMMIT();
        } else {
            CP_COMMIT();   // keep group count balanced
        }

        uint32_t a_base = smem_u + buf * STAGE_BYTES;
        uint32_t b_base = a_base + HALF_BYTES;
#pragma unroll
        for (int kk = 0; kk < BK; kk += 16) {
            uint32_t af[4][4], bf[4][2];
#pragma unroll
            for (int mt = 0; mt < 4; mt++) {
                uint32_t addr = a_base +
                    ((wm * 64 + mt * 16 + lr) * KPADH + kk + lk) * 2;
                ldsm4(af[mt], addr);
            }
#pragma unroll
            for (int p = 0; p < 2; p++) {
                uint32_t r[4];
                uint32_t addr = b_base +
                    ((wn * 32 + p * 16 + lr) * KPADH + kk + lk) * 2;
                ldsm4(r, addr);
                bf[2 * p][0] = r[0];     bf[2 * p][1] = r[2];
                bf[2 * p + 1][0] = r[1]; bf[2 * p + 1][1] = r[3];
            }
#pragma unroll
            for (int mt = 0; mt < 4; mt++)
#pragma unroll
                for (int nt = 0; nt < 4; nt++)
                    mma16816(c[mt][nt], af[mt], bf[nt]);
        }
        buf = (buf + 1 == STG) ? 0 : buf + 1;
    }

    // epilogue (f32)
#pragma unroll
    for (int mt = 0; mt < 4; mt++) {
        int r0 = bm * 128 + wm * 64 + mt * 16 + gid;
#pragma unroll
        for (int nt = 0; nt < 4; nt++) {
            int col = bn * 128 + wn * 32 + nt * 8 + tig * 2;
            *(float2*)(&C[(size_t)r0 * 1024 + col]) = make_float2(c[mt][nt][0], c[mt][nt][1]);
            *(float2*)(&C[(size_t)(r0 + 8) * 1024 + col]) = make_float2(c[mt][nt][2], c[mt][nt][3]);
        }
    }
}

// ---------------------------------------------------------------------------
// 5) Scan phase 1
// ---------------------------------------------------------------------------
__global__ void scan_partial() {
    int bh = blockIdx.y;
    int ch = blockIdx.x;
    int a = threadIdx.x;
    int b = bh >> 4, h = bh & 15;
    const float* cr = g_cross + bh * N_;
    int n0 = ch * 128;
    float sc = 0.f, scv = 0.f;
#pragma unroll 4
    for (int i = 0; i < 128; i++) {
        int n = n0 + i;
        float cn = cr[n];
        float v = g_values[((size_t)(b * N_ + n) * H_ + h) * A_ + a];
        sc += cn;
        scv = fmaf(cn, v, scv);
    }
    g_psum_cv[(bh * 32 + ch) * A_ + a] = scv;
    if (a == 0) g_psum_c[bh * 32 + ch] = sc;
}

// ---------------------------------------------------------------------------
// 6) Scan phase 2
// ---------------------------------------------------------------------------
__global__ void scan_prefix() {
    int bh = blockIdx.x;
    int a = threadIdx.x;
    float run = 0.f;
    for (int ch = 0; ch < 32; ch++) {
        int idx = (bh * 32 + ch) * A_ + a;
        float v = g_psum_cv[idx];
        g_psum_cv[idx] = run;
        run += v;
    }
    if (a == 0) {
        float rc = 0.f;
        for (int ch = 0; ch < 32; ch++) {
            float v = g_psum_c[bh * 32 + ch];
            g_psum_c[bh * 32 + ch] = rc;
            rc += v;
        }
    }
}

// ---------------------------------------------------------------------------
// 7) Scan phase 3 (stores fp16 for GEMM2)
// ---------------------------------------------------------------------------
__global__ void scan_final() {
    int bh = blockIdx.y;
    int ch = blockIdx.x;
    int a = threadIdx.x;
    int b = bh >> 4, h = bh & 15;
    float run_cv = g_psum_cv[(bh * 32 + ch) * A_ + a];
    float run_c = g_psum_c[bh * 32 + ch];
    const float* cr = g_cross + bh * N_;
    const float* dg = g_diag + bh * N_;
    const float* ex = g_extra + bh * N_;
    const float* pe = g_p2e + h * N_;
    int n0 = ch * 128;
#pragma unroll 4
    for (int i = 0; i < 128; i++) {
        int n = n0 + i;
        float cn = cr[n];
        float dn = dg[n];
        float peE = pe[n] * ex[n];
        size_t vidx = ((size_t)(b * N_ + n) * H_ + h) * A_ + a;
        float v = g_values[vidx];
        run_cv = fmaf(cn, v, run_cv);
        run_c += cn;
        float num = fmaf(run_cv, peE, v * dn);
        float den = fmaf(run_c, peE, dn);
        g_outh[vidx] = __float2half_rn(num / den);
    }
}

// ---------------------------------------------------------------------------
// Launcher
// ---------------------------------------------------------------------------
extern "C" void kernel_launch(void* const* d_in, const int* in_sizes, int n_in,
                              void* d_out, int out_size) {
    const float* x  = (const float*)d_in[0];
    const float* k1 = (const float*)d_in[1];
    const float* k2 = (const float*)d_in[2];
    const float* k3 = (const float*)d_in[3];
    const float* a1 = (const float*)d_in[4];
    const float* a2 = (const float*)d_in[5];
    const float* b1 = (const float*)d_in[6];
    const float* b2 = (const float*)d_in[7];
    const float* cc = (const float*)d_in[8];
    const float* vw = (const float*)d_in[9];
    const float* ow = (const float*)d_in[10];
    float* out = (float*)d_out;

    void *p_wvh, *p_woh, *p_values, *p_outh, *p_xh;
    cudaGetSymbolAddress(&p_wvh, g_wv_h);
    cudaGetSymbolAddress(&p_woh, g_wo_h);
    cudaGetSymbolAddress(&p_values, g_values);
    cudaGetSymbolAddress(&p_outh, g_outh);
    cudaGetSymbolAddress(&p_xh, g_xh);

    cudaFuncSetAttribute(gemm_f16, cudaFuncAttributeMaxDynamicSharedMemorySize, GSMEM);

    transpose_weights<<<(1024 * 1024) / 256, 256>>>(vw, ow);
    pos_kernel<<<(H_ * N_) / 256, 256>>>(a1, a2, b1, b2, cc);
    proj_kernel<<<M_, 256>>>(x, k1, k2, k3);

    // values = x @ Wv^T  -> [b,n,h,a]
    gemm_f16<<<dim3(8, 128), 256, GSMEM>>>((const __half*)p_xh, (const __half*)p_wvh,
                                           (float*)p_values);

    scan_partial<<<dim3(32, B_ * H_), A_>>>();
    scan_prefix<<<B_ * H_, A_>>>();
    scan_final<<<dim3(32, B_ * H_), A_>>>();

    // result = outh @ Wo^T -> d_out
    gemm_f16<<<dim3(8, 128), 256, GSMEM>>>((const __half*)p_outh,
                                           (const __half*)p_woh, out);
}

// round 6
// speedup vs baseline: 3.7797x; 1.0798x over previous
#include <cuda_runtime.h>
#include <cuda_fp16.h>
#include <math.h>
#include <stdint.h>

// Problem shapes (fixed)
#define B_ 4
#define N_ 4096
#define W_ 1024
#define H_ 16
#define A_ 64
#define HA_ 1024           // H_*A_
#define M_ 16384           // B_*N_
#define NCH 64             // scan chunks per sequence
#define CLEN (N_ / NCH)    // 64 n per chunk

// ---------------------------------------------------------------------------
// Scratch (no allocations allowed -> __device__ globals)
// ---------------------------------------------------------------------------
__device__ __half g_valh[M_ * HA_];         // [b,n,h,a]  32 MB (GEMM1 out, fp16)
__device__ __half g_outh[M_ * HA_];         // [b,n,h,a]  32 MB (GEMM2 in, fp16)
__device__ __half g_xh[M_ * W_];            // fp16 x, 32 MB
__device__ __half g_wv_h[HA_ * W_];         // [n=h*A+a][k=w]  2 MB
__device__ __half g_wo_h[W_ * HA_];         // [n=w][k=h*A+a]  2 MB
__device__ float g_cross[B_ * H_ * N_];     // exp'd, [b,h,n]
__device__ float g_diag [B_ * H_ * N_];
__device__ float g_extra[B_ * H_ * N_];
__device__ float g_p1 [H_ * N_];
__device__ float g_p2e[H_ * N_];            // exp'd
__device__ float g_psum_cv[B_ * H_ * NCH * A_];
__device__ float g_psum_c [B_ * H_ * NCH];

__device__ __forceinline__ uint32_t s2u(const void* p) {
    uint32_t r;
    asm("{ .reg .u64 t; cvta.to.shared.u64 t, %1; cvt.u32.u64 %0, t; }" : "=r"(r) : "l"(p));
    return r;
}
__device__ __forceinline__ void cp16(uint32_t dst, const void* src) {
    asm volatile("cp.async.cg.shared.global [%0], [%1], 16;" :: "r"(dst), "l"(src));
}
#define CP_COMMIT() asm volatile("cp.async.commit_group;" ::: "memory")
#define CP_WAIT(n)  asm volatile("cp.async.wait_group %0;" :: "n"(n) : "memory")

// ---------------------------------------------------------------------------
// 1a) Wv transpose (w <-> a within each h), smem tiled, fully coalesced:
//     g_wv_h[(h*64+a)*1024 + w] = vw[h,w,a]
// ---------------------------------------------------------------------------
__global__ void transpose_wv(const float* __restrict__ vw) {
    __shared__ float tile[32][33];
    int h = blockIdx.z;
    int w0 = blockIdx.x * 32;
    int a0 = blockIdx.y * 32;
    int tx = threadIdx.x, ty = threadIdx.y;     // 32 x 8
#pragma unroll
    for (int i = 0; i < 4; i++) {
        int w = w0 + ty + i * 8;
        tile[ty + i * 8][tx] = vw[((h << 10) + w) * 64 + a0 + tx];
    }
    __syncthreads();
#pragma unroll
    for (int i = 0; i < 4; i++) {
        int a = a0 + ty + i * 8;
        g_wv_h[((h << 6) + a) * 1024 + w0 + tx] = __float2half_rn(tile[tx][ty + i * 8]);
    }
}

// ---------------------------------------------------------------------------
// 1b) Wo permuted copy (contiguous in a on both sides):
//     g_wo_h[w*1024 + h*64 + a] = ow[h,w,a]
// ---------------------------------------------------------------------------
__global__ void transpose_wo(const float* __restrict__ ow) {
    int i2 = (blockIdx.x * blockDim.x + threadIdx.x) * 2;  // dst linear, 2 elems
    int a = i2 & 63;
    int hq = (i2 >> 6) & 15;
    int w = i2 >> 10;
    float2 v = *(const float2*)(ow + (size_t)(((hq << 10) + w) << 6) + a);
    *(__half2*)(g_wo_h + i2) = __floats2half2_rn(v.x, v.y);
}

// ---------------------------------------------------------------------------
// 2) Positional
// ---------------------------------------------------------------------------
__global__ void pos_kernel(const float* __restrict__ a1, const float* __restrict__ a2,
                           const float* __restrict__ b1, const float* __restrict__ b2,
                           const float* __restrict__ cc) {
    int idx = blockIdx.x * blockDim.x + threadIdx.x;
    int h = idx >> 12;
    int n = idx & (N_ - 1);
    float nv = (float)n * (1.0f / 4095.0f);
    float s1 = 0.f, s2 = 0.f;
#pragma unroll 8
    for (int p = 0; p < 64; p++) {
        float cp = cc[h * 64 + p];
        s1 += sinf(fmaf(a1[h * 64 + p], nv, b1[h * 64 + p])) * cp;
        s2 += sinf(fmaf(a2[h * 64 + p], nv, b2[h * 64 + p])) * cp;
    }
    g_p1[idx] = s1;
    s2 = fminf(fmaxf(s2, -20.f), 20.f);
    g_p2e[idx] = expf(s2);
}

// ---------------------------------------------------------------------------
// 3) Projections (+ writes fp16 x copy for GEMM1)
// ---------------------------------------------------------------------------
__global__ __launch_bounds__(256) void proj_kernel(const float* __restrict__ x,
                                                   const float* __restrict__ k1,
                                                   const float* __restrict__ k2,
                                                   const float* __restrict__ k3) {
    __shared__ float xs[W_];
    int row = blockIdx.x;
    const float4* xr = (const float4*)(x + (size_t)row * W_);
    float4* xs4 = (float4*)xs;
    float4 v = xr[threadIdx.x];
    xs4[threadIdx.x] = v;
    __half2 h0 = __floats2half2_rn(v.x, v.y);
    __half2 h1 = __floats2half2_rn(v.z, v.w);
    *(uint2*)(g_xh + (size_t)row * W_ + threadIdx.x * 4) =
        make_uint2(*(uint32_t*)&h0, *(uint32_t*)&h1);
    __syncthreads();

    int warp = threadIdx.x >> 5;
    int lane = threadIdx.x & 31;
    int b = row >> 12;
    int n = row & (N_ - 1);

    for (int j = warp; j < 48; j += 8) {
        int which = j >> 4;
        int h = j & 15;
        const float* kk = (which == 0) ? k1 : ((which == 1) ? k2 : k3);
        const float* kh = kk + h * W_;
        float s = 0.f;
#pragma unroll 8
        for (int i = lane; i < W_; i += 32) s += xs[i] * kh[i];
#pragma unroll
        for (int o = 16; o; o >>= 1) s += __shfl_xor_sync(0xffffffffu, s, o);
        if (lane == 0) {
            if (which == 0) s += g_p1[h * N_ + n];
            s = fminf(fmaxf(s, -20.f), 20.f);
            s = expf(s);
            int off = (b * H_ + h) * N_ + n;
            if (which == 0)      g_cross[off] = s;
            else if (which == 1) g_diag[off]  = s;
            else                 g_extra[off] = s;
        }
    }
}

// ---------------------------------------------------------------------------
// 4/7) fp16 mma.m16n8k16 GEMM, cp.async 4-stage pipeline, ldmatrix fragments.
//      C[M,1024] = A[M,1024] @ Bt[1024,1024]^T, templated output type.
// ---------------------------------------------------------------------------
#define BK 32
#define KPADH 40                       // halves per smem row (80 B)
#define KT2 (1024 / BK)                // 32 k-tiles
#define STG 4
#define HALF_BYTES (128 * KPADH * 2)   // one matrix tile: 10240 B
#define STAGE_BYTES (2 * HALF_BYTES)   // 20480 B
#define GSMEM (STG * STAGE_BYTES)      // 81920 B

__device__ __forceinline__ void mma16816(float* c, const uint32_t* a, const uint32_t* b) {
    asm volatile(
        "mma.sync.aligned.m16n8k16.row.col.f32.f16.f16.f32 "
        "{%0,%1,%2,%3}, {%4,%5,%6,%7}, {%8,%9}, {%0,%1,%2,%3};"
        : "+f"(c[0]), "+f"(c[1]), "+f"(c[2]), "+f"(c[3])
        : "r"(a[0]), "r"(a[1]), "r"(a[2]), "r"(a[3]), "r"(b[0]), "r"(b[1]));
}
__device__ __forceinline__ void ldsm4(uint32_t* r, uint32_t addr) {
    asm volatile("ldmatrix.sync.aligned.m8n8.x4.shared.b16 {%0,%1,%2,%3}, [%4];"
                 : "=r"(r[0]), "=r"(r[1]), "=r"(r[2]), "=r"(r[3]) : "r"(addr));
}

template <typename OutT>
__global__ __launch_bounds__(256, 2) void gemm_f16(const __half* __restrict__ A,
                                                   const __half* __restrict__ Bt,
                                                   OutT* __restrict__ C) {
    extern __shared__ __align__(16) char smem[];
    uint32_t smem_u = s2u(smem);

    int tid = threadIdx.x;
    int lane = tid & 31, wid = tid >> 5;
    int wm = wid >> 2;            // 0..1
    int wn = wid & 3;             // 0..3
    int gid = lane >> 2;          // 0..7
    int tig = lane & 3;           // 0..3
    int lr = lane & 15;
    int lk = (lane >> 4) << 3;

    int bn = blockIdx.x, bm = blockIdx.y;
    const __half* Ag = A + (size_t)(bm * 128) * 1024;
    const __half* Bg = Bt + (size_t)(bn * 128) * 1024;

    int c0row = tid >> 2;
    int c0k = (tid & 3) * 8;

    float c[4][4][4];
#pragma unroll
    for (int i = 0; i < 4; i++)
#pragma unroll
        for (int j = 0; j < 4; j++)
#pragma unroll
            for (int q = 0; q < 4; q++) c[i][j][q] = 0.f;

    auto load_stage = [&](int t, int s) {
        int k0 = t * BK;
        uint32_t base = smem_u + s * STAGE_BYTES;
#pragma unroll
        for (int i = 0; i < 2; i++) {
            int row = c0row + i * 64;
            uint32_t off = (uint32_t)(row * (KPADH * 2) + c0k * 2);
            cp16(base + off, Ag + (size_t)row * 1024 + k0 + c0k);
            cp16(base + HALF_BYTES + off, Bg + (size_t)row * 1024 + k0 + c0k);
        }
    };

#pragma unroll
    for (int s = 0; s < STG - 1; s++) {
        load_stage(s, s);
        CP_COMMIT();
    }

    int buf = 0;
    for (int t = 0; t < KT2; t++) {
        CP_WAIT(STG - 2);
        __syncthreads();
        if (t + STG - 1 < KT2) {
            int nb = buf + (STG - 1);
            if (nb >= STG) nb -= STG;
            load_stage(t + STG - 1, nb);
            CP_COMMIT();
        } else {
            CP_COMMIT();
        }

        uint32_t a_base = smem_u + buf * STAGE_BYTES;
        uint32_t b_base = a_base + HALF_BYTES;
#pragma unroll
        for (int kk = 0; kk < BK; kk += 16) {
            uint32_t af[4][4], bf[4][2];
#pragma unroll
            for (int mt = 0; mt < 4; mt++) {
                uint32_t addr = a_base +
                    ((wm * 64 + mt * 16 + lr) * KPADH + kk + lk) * 2;
                ldsm4(af[mt], addr);
            }
#pragma unroll
            for (int p = 0; p < 2; p++) {
                uint32_t r[4];
                uint32_t addr = b_base +
                    ((wn * 32 + p * 16 + lr) * KPADH + kk + lk) * 2;
                ldsm4(r, addr);
                bf[2 * p][0] = r[0];     bf[2 * p][1] = r[2];
                bf[2 * p + 1][0] = r[1]; bf[2 * p + 1][1] = r[3];
            }
#pragma unroll
            for (int mt = 0; mt < 4; mt++)
#pragma unroll
                for (int nt = 0; nt < 4; nt++)
                    mma16816(c[mt][nt], af[mt], bf[nt]);
        }
        buf = (buf + 1 == STG) ? 0 : buf + 1;
    }

    // epilogue
#pragma unroll
    for (int mt = 0; mt < 4; mt++) {
        int r0 = bm * 128 + wm * 64 + mt * 16 + gid;
#pragma unroll
        for (int nt = 0; nt < 4; nt++) {
            int col = bn * 128 + wn * 32 + nt * 8 + tig * 2;
            if (sizeof(OutT) == 4) {
                *(float2*)((float*)C + (size_t)r0 * 1024 + col) =
                    make_float2(c[mt][nt][0], c[mt][nt][1]);
                *(float2*)((float*)C + (size_t)(r0 + 8) * 1024 + col) =
                    make_float2(c[mt][nt][2], c[mt][nt][3]);
            } else {
                *(__half2*)((__half*)C + (size_t)r0 * 1024 + col) =
                    __floats2half2_rn(c[mt][nt][0], c[mt][nt][1]);
                *(__half2*)((__half*)C + (size_t)(r0 + 8) * 1024 + col) =
                    __floats2half2_rn(c[mt][nt][2], c[mt][nt][3]);
            }
        }
    }
}

// ---------------------------------------------------------------------------
// 5) Scan phase 1: per (bh, chunk of 64 n): partial sums
// ---------------------------------------------------------------------------
__global__ void scan_partial() {
    int bh = blockIdx.y;
    int ch = blockIdx.x;
    int a = threadIdx.x;
    int b = bh >> 4, h = bh & 15;
    const float* cr = g_cross + bh * N_;
    int n0 = ch * CLEN;
    float sc = 0.f, scv = 0.f;
#pragma unroll 8
    for (int i = 0; i < CLEN; i++) {
        int n = n0 + i;
        float cn = cr[n];
        float v = __half2float(g_valh[((size_t)(b * N_ + n) * H_ + h) * A_ + a]);
        sc += cn;
        scv = fmaf(cn, v, scv);
    }
    g_psum_cv[(bh * NCH + ch) * A_ + a] = scv;
    if (a == 0) g_psum_c[bh * NCH + ch] = sc;
}

// ---------------------------------------------------------------------------
// 6) Scan phase 2: register-resident exclusive prefix over NCH chunks
// ---------------------------------------------------------------------------
__global__ void scan_prefix() {
    int bh = blockIdx.x;
    int a = threadIdx.x;                 // 0..63
    float r[NCH];
#pragma unroll
    for (int ch = 0; ch < NCH; ch++)
        r[ch] = g_psum_cv[(bh * NCH + ch) * A_ + a];
    float run = 0.f;
#pragma unroll
    for (int ch = 0; ch < NCH; ch++) { float t = r[ch]; r[ch] = run; run += t; }
#pragma unroll
    for (int ch = 0; ch < NCH; ch++)
        g_psum_cv[(bh * NCH + ch) * A_ + a] = r[ch];
    if (a == 0) {
        float rc[NCH];
#pragma unroll
        for (int ch = 0; ch < NCH; ch++) rc[ch] = g_psum_c[bh * NCH + ch];
        float run2 = 0.f;
#pragma unroll
        for (int ch = 0; ch < NCH; ch++) { float t = rc[ch]; rc[ch] = run2; run2 += t; }
#pragma unroll
        for (int ch = 0; ch < NCH; ch++) g_psum_c[bh * NCH + ch] = rc[ch];
    }
}

// ---------------------------------------------------------------------------
// 7) Scan phase 3: rescan chunk with carried prefix (stores fp16 for GEMM2)
// ---------------------------------------------------------------------------
__global__ void scan_final() {
    int bh = blockIdx.y;
    int ch = blockIdx.x;
    int a = threadIdx.x;
    int b = bh >> 4, h = bh & 15;
    float run_cv = g_psum_cv[(bh * NCH + ch) * A_ + a];
    float run_c = g_psum_c[bh * NCH + ch];
    const float* cr = g_cross + bh * N_;
    const float* dg = g_diag + bh * N_;
    const float* ex = g_extra + bh * N_;
    const float* pe = g_p2e + h * N_;
    int n0 = ch * CLEN;
#pragma unroll 8
    for (int i = 0; i < CLEN; i++) {
        int n = n0 + i;
        float cn = cr[n];
        float dn = dg[n];
        float peE = pe[n] * ex[n];
        size_t vidx = ((size_t)(b * N_ + n) * H_ + h) * A_ + a;
        float v = __half2float(g_valh[vidx]);
        run_cv = fmaf(cn, v, run_cv);
        run_c += cn;
        float num = fmaf(run_cv, peE, v * dn);
        float den = fmaf(run_c, peE, dn);
        g_outh[vidx] = __float2half_rn(num / den);
    }
}

// ---------------------------------------------------------------------------
// Launcher
// ---------------------------------------------------------------------------
extern "C" void kernel_launch(void* const* d_in, const int* in_sizes, int n_in,
                              void* d_out, int out_size) {
    const float* x  = (const float*)d_in[0];
    const float* k1 = (const float*)d_in[1];
    const float* k2 = (const float*)d_in[2];
    const float* k3 = (const float*)d_in[3];
    const float* a1 = (const float*)d_in[4];
    const float* a2 = (const float*)d_in[5];
    const float* b1 = (const float*)d_in[6];
    const float* b2 = (const float*)d_in[7];
    const float* cc = (const float*)d_in[8];
    const float* vw = (const float*)d_in[9];
    const float* ow = (const float*)d_in[10];
    float* out = (float*)d_out;

    void *p_wvh, *p_woh, *p_valh, *p_outh, *p_xh;
    cudaGetSymbolAddress(&p_wvh, g_wv_h);
    cudaGetSymbolAddress(&p_woh, g_wo_h);
    cudaGetSymbolAddress(&p_valh, g_valh);
    cudaGetSymbolAddress(&p_outh, g_outh);
    cudaGetSymbolAddress(&p_xh, g_xh);

    cudaFuncSetAttribute(gemm_f16<__half>, cudaFuncAttributeMaxDynamicSharedMemorySize, GSMEM);
    cudaFuncSetAttribute(gemm_f16<float>, cudaFuncAttributeMaxDynamicSharedMemorySize, GSMEM);

    transpose_wv<<<dim3(32, 2, 16), dim3(32, 8)>>>(vw);
    transpose_wo<<<2048, 256>>>(ow);
    pos_kernel<<<(H_ * N_) / 256, 256>>>(a1, a2, b1, b2, cc);
    proj_kernel<<<M_, 256>>>(x, k1, k2, k3);

    // values = x @ Wv^T  -> [b,n,h,a] fp16
    gemm_f16<__half><<<dim3(8, 128), 256, GSMEM>>>((const __half*)p_xh,
                                                   (const __half*)p_wvh,
                                                   (__half*)p_valh);

    scan_partial<<<dim3(NCH, B_ * H_), A_>>>();
    scan_prefix<<<B_ * H_, A_>>>();
    scan_final<<<dim3(NCH, B_ * H_), A_>>>();

    // result = outh @ Wo^T -> d_out (f32)
    gemm_f16<float><<<dim3(8, 128), 256, GSMEM>>>((const __half*)p_outh,
                                                  (const __half*)p_woh, out);
}

// round 7
// speedup vs baseline: 4.8093x; 1.2724x over previous
#include <cuda_runtime.h>
#include <cuda_fp16.h>
#include <math.h>
#include <stdint.h>

// Problem shapes (fixed)
#define B_ 4
#define N_ 4096
#define W_ 1024
#define H_ 16
#define A_ 64
#define HA_ 1024           // H_*A_
#define M_ 16384           // B_*N_
#define NCH 64             // scan chunks per sequence
#define CLEN (N_ / NCH)    // 64 n per chunk

// ---------------------------------------------------------------------------
// Scratch (no allocations allowed -> __device__ globals)
// ---------------------------------------------------------------------------
__device__ __half g_valh[M_ * HA_];         // [b,n,h,a]  32 MB (GEMM1 out, fp16)
__device__ __half g_outh[M_ * HA_];         // [b,n,h,a]  32 MB (GEMM2 in, fp16)
__device__ __half g_xh[M_ * W_];            // fp16 x, 32 MB
__device__ __half g_wv_h[HA_ * W_];         // [n=h*A+a][k=w]  2 MB
__device__ __half g_wo_h[W_ * HA_];         // [n=w][k=h*A+a]  2 MB
__device__ float g_cross[B_ * H_ * N_];     // exp'd, [b,h,n]
__device__ float g_diag [B_ * H_ * N_];
__device__ float g_extra[B_ * H_ * N_];
__device__ float g_p1 [H_ * N_];
__device__ float g_p2e[H_ * N_];            // exp'd
__device__ float g_psum_cv[B_ * H_ * NCH * A_];
__device__ float g_psum_c [B_ * H_ * NCH];

__device__ __forceinline__ uint32_t s2u(const void* p) {
    uint32_t r;
    asm("{ .reg .u64 t; cvta.to.shared.u64 t, %1; cvt.u32.u64 %0, t; }" : "=r"(r) : "l"(p));
    return r;
}
__device__ __forceinline__ void cp16(uint32_t dst, const void* src) {
    asm volatile("cp.async.cg.shared.global [%0], [%1], 16;" :: "r"(dst), "l"(src));
}
#define CP_COMMIT() asm volatile("cp.async.commit_group;" ::: "memory")
#define CP_WAIT(n)  asm volatile("cp.async.wait_group %0;" :: "n"(n) : "memory")

// ---------------------------------------------------------------------------
// 1a) Wv transpose, smem tiled, coalesced
// ---------------------------------------------------------------------------
__global__ void transpose_wv(const float* __restrict__ vw) {
    __shared__ float tile[32][33];
    int h = blockIdx.z;
    int w0 = blockIdx.x * 32;
    int a0 = blockIdx.y * 32;
    int tx = threadIdx.x, ty = threadIdx.y;     // 32 x 8
#pragma unroll
    for (int i = 0; i < 4; i++) {
        int w = w0 + ty + i * 8;
        tile[ty + i * 8][tx] = vw[((h << 10) + w) * 64 + a0 + tx];
    }
    __syncthreads();
#pragma unroll
    for (int i = 0; i < 4; i++) {
        int a = a0 + ty + i * 8;
        g_wv_h[((h << 6) + a) * 1024 + w0 + tx] = __float2half_rn(tile[tx][ty + i * 8]);
    }
}

// ---------------------------------------------------------------------------
// 1b) Wo permuted copy
// ---------------------------------------------------------------------------
__global__ void transpose_wo(const float* __restrict__ ow) {
    int i2 = (blockIdx.x * blockDim.x + threadIdx.x) * 2;
    int a = i2 & 63;
    int hq = (i2 >> 6) & 15;
    int w = i2 >> 10;
    float2 v = *(const float2*)(ow + (size_t)(((hq << 10) + w) << 6) + a);
    *(__half2*)(g_wo_h + i2) = __floats2half2_rn(v.x, v.y);
}

// ---------------------------------------------------------------------------
// 2) Positional
// ---------------------------------------------------------------------------
__global__ void pos_kernel(const float* __restrict__ a1, const float* __restrict__ a2,
                           const float* __restrict__ b1, const float* __restrict__ b2,
                           const float* __restrict__ cc) {
    int idx = blockIdx.x * blockDim.x + threadIdx.x;
    int h = idx >> 12;
    int n = idx & (N_ - 1);
    float nv = (float)n * (1.0f / 4095.0f);
    float s1 = 0.f, s2 = 0.f;
#pragma unroll 8
    for (int p = 0; p < 64; p++) {
        float cp = cc[h * 64 + p];
        s1 += sinf(fmaf(a1[h * 64 + p], nv, b1[h * 64 + p])) * cp;
        s2 += sinf(fmaf(a2[h * 64 + p], nv, b2[h * 64 + p])) * cp;
    }
    g_p1[idx] = s1;
    s2 = fminf(fmaxf(s2, -20.f), 20.f);
    g_p2e[idx] = expf(s2);
}

// ---------------------------------------------------------------------------
// 3) Projection GEMM: Z[16384, 48] = x[16384,1024] @ Kmat[1024,48]
//    cols 0..15 = k1 heads, 16..31 = k2, 32..47 = k3. fp32, register tiled.
//    Also writes the fp16 copy of x for GEMM1. Epilogue: +p1/clip/exp scatter.
// ---------------------------------------------------------------------------
#define PROWS 128
#define PKC 128
#define XPITCH 132
#define KPITCH 133
#define PSMEM ((PROWS * XPITCH + 48 * KPITCH) * 4)

__global__ __launch_bounds__(512) void proj_gemm(const float* __restrict__ x,
                                                 const float* __restrict__ k1,
                                                 const float* __restrict__ k2,
                                                 const float* __restrict__ k3) {
    extern __shared__ __align__(16) float ps[];
    float* xs = ps;                       // [PROWS][XPITCH]
    float* ks = ps + PROWS * XPITCH;      // [48][KPITCH]

    int tid = threadIdx.x;
    int row0 = blockIdx.x * PROWS;
    int tr = tid >> 3;                    // 0..63 -> rows tr*2, tr*2+1
    int tc = tid & 7;                     // 0..7  -> cols tc*6..tc*6+5

    const float* kmat[3] = {k1, k2, k3};

    float acc[2][6];
#pragma unroll
    for (int i = 0; i < 2; i++)
#pragma unroll
        for (int j = 0; j < 6; j++) acc[i][j] = 0.f;

    for (int k0 = 0; k0 < W_; k0 += PKC) {
        // fill x tile (and fp16 shadow of x)
#pragma unroll
        for (int i = 0; i < 8; i++) {
            int f = tid + i * 512;            // 0..4095 float4s
            int r = f >> 5, c4 = (f & 31) * 4;
            float4 v = *(const float4*)(x + (size_t)(row0 + r) * W_ + k0 + c4);
            *(float4*)(xs + r * XPITCH + c4) = v;
            __half2 h0 = __floats2half2_rn(v.x, v.y);
            __half2 h1 = __floats2half2_rn(v.z, v.w);
            *(uint2*)(g_xh + (size_t)(row0 + r) * W_ + k0 + c4) =
                make_uint2(*(uint32_t*)&h0, *(uint32_t*)&h1);
        }
        // fill k tile
        for (int i = tid; i < 48 * PKC; i += 512) {
            int j = i >> 7;                   // col 0..47
            int kk = i & (PKC - 1);
            ks[j * KPITCH + kk] = kmat[j >> 4][(j & 15) * W_ + k0 + kk];
        }
        __syncthreads();

        const float* xp0 = xs + (tr * 2) * XPITCH;
        const float* xp1 = xp0 + XPITCH;
        const float* kp = ks + (tc * 6) * KPITCH;
#pragma unroll 4
        for (int kk = 0; kk < PKC; kk++) {
            float x0 = xp0[kk], x1 = xp1[kk];
            float kv[6];
#pragma unroll
            for (int j = 0; j < 6; j++) kv[j] = kp[j * KPITCH + kk];
#pragma unroll
            for (int j = 0; j < 6; j++) {
                acc[0][j] = fmaf(x0, kv[j], acc[0][j]);
                acc[1][j] = fmaf(x1, kv[j], acc[1][j]);
            }
        }
        __syncthreads();
    }

    // epilogue: add p1 (cross only), clip, exp, scatter to [b,h,n]
#pragma unroll
    for (int i = 0; i < 2; i++) {
        int row = row0 + tr * 2 + i;
        int b = row >> 12, n = row & (N_ - 1);
#pragma unroll
        for (int j = 0; j < 6; j++) {
            int col = tc * 6 + j;
            int which = col >> 4, h = col & 15;
            float s = acc[i][j];
            if (which == 0) s += g_p1[h * N_ + n];
            s = fminf(fmaxf(s, -20.f), 20.f);
            s = expf(s);
            int off = (b * H_ + h) * N_ + n;
            if (which == 0)      g_cross[off] = s;
            else if (which == 1) g_diag[off]  = s;
            else                 g_extra[off] = s;
        }
    }
}

// ---------------------------------------------------------------------------
// 4/7) fp16 mma.m16n8k16 GEMM, cp.async 4-stage pipeline, ldmatrix fragments.
// ---------------------------------------------------------------------------
#define BK 32
#define KPADH 40
#define KT2 (1024 / BK)
#define STG 4
#define HALF_BYTES (128 * KPADH * 2)
#define STAGE_BYTES (2 * HALF_BYTES)
#define GSMEM (STG * STAGE_BYTES)

__device__ __forceinline__ void mma16816(float* c, const uint32_t* a, const uint32_t* b) {
    asm volatile(
        "mma.sync.aligned.m16n8k16.row.col.f32.f16.f16.f32 "
        "{%0,%1,%2,%3}, {%4,%5,%6,%7}, {%8,%9}, {%0,%1,%2,%3};"
        : "+f"(c[0]), "+f"(c[1]), "+f"(c[2]), "+f"(c[3])
        : "r"(a[0]), "r"(a[1]), "r"(a[2]), "r"(a[3]), "r"(b[0]), "r"(b[1]));
}
__device__ __forceinline__ void ldsm4(uint32_t* r, uint32_t addr) {
    asm volatile("ldmatrix.sync.aligned.m8n8.x4.shared.b16 {%0,%1,%2,%3}, [%4];"
                 : "=r"(r[0]), "=r"(r[1]), "=r"(r[2]), "=r"(r[3]) : "r"(addr));
}

template <typename OutT>
__global__ __launch_bounds__(256, 2) void gemm_f16(const __half* __restrict__ A,
                                                   const __half* __restrict__ Bt,
                                                   OutT* __restrict__ C) {
    extern __shared__ __align__(16) char smem[];
    uint32_t smem_u = s2u(smem);

    int tid = threadIdx.x;
    int lane = tid & 31, wid = tid >> 5;
    int wm = wid >> 2;
    int wn = wid & 3;
    int gid = lane >> 2;
    int tig = lane & 3;
    int lr = lane & 15;
    int lk = (lane >> 4) << 3;

    int bn = blockIdx.x, bm = blockIdx.y;
    const __half* Ag = A + (size_t)(bm * 128) * 1024;
    const __half* Bg = Bt + (size_t)(bn * 128) * 1024;

    int c0row = tid >> 2;
    int c0k = (tid & 3) * 8;

    float c[4][4][4];
#pragma unroll
    for (int i = 0; i < 4; i++)
#pragma unroll
        for (int j = 0; j < 4; j++)
#pragma unroll
            for (int q = 0; q < 4; q++) c[i][j][q] = 0.f;

    auto load_stage = [&](int t, int s) {
        int k0 = t * BK;
        uint32_t base = smem_u + s * STAGE_BYTES;
#pragma unroll
        for (int i = 0; i < 2; i++) {
            int row = c0row + i * 64;
            uint32_t off = (uint32_t)(row * (KPADH * 2) + c0k * 2);
            cp16(base + off, Ag + (size_t)row * 1024 + k0 + c0k);
            cp16(base + HALF_BYTES + off, Bg + (size_t)row * 1024 + k0 + c0k);
        }
    };

#pragma unroll
    for (int s = 0; s < STG - 1; s++) {
        load_stage(s, s);
        CP_COMMIT();
    }

    int buf = 0;
    for (int t = 0; t < KT2; t++) {
        CP_WAIT(STG - 2);
        __syncthreads();
        if (t + STG - 1 < KT2) {
            int nb = buf + (STG - 1);
            if (nb >= STG) nb -= STG;
            load_stage(t + STG - 1, nb);
            CP_COMMIT();
        } else {
            CP_COMMIT();
        }

        uint32_t a_base = smem_u + buf * STAGE_BYTES;
        uint32_t b_base = a_base + HALF_BYTES;
#pragma unroll
        for (int kk = 0; kk < BK; kk += 16) {
            uint32_t af[4][4], bf[4][2];
#pragma unroll
            for (int mt = 0; mt < 4; mt++) {
                uint32_t addr = a_base +
                    ((wm * 64 + mt * 16 + lr) * KPADH + kk + lk) * 2;
                ldsm4(af[mt], addr);
            }
#pragma unroll
            for (int p = 0; p < 2; p++) {
                uint32_t r[4];
                uint32_t addr = b_base +
                    ((wn * 32 + p * 16 + lr) * KPADH + kk + lk) * 2;
                ldsm4(r, addr);
                bf[2 * p][0] = r[0];     bf[2 * p][1] = r[2];
                bf[2 * p + 1][0] = r[1]; bf[2 * p + 1][1] = r[3];
            }
#pragma unroll
            for (int mt = 0; mt < 4; mt++)
#pragma unroll
                for (int nt = 0; nt < 4; nt++)
                    mma16816(c[mt][nt], af[mt], bf[nt]);
        }
        buf = (buf + 1 == STG) ? 0 : buf + 1;
    }

#pragma unroll
    for (int mt = 0; mt < 4; mt++) {
        int r0 = bm * 128 + wm * 64 + mt * 16 + gid;
#pragma unroll
        for (int nt = 0; nt < 4; nt++) {
            int col = bn * 128 + wn * 32 + nt * 8 + tig * 2;
            if (sizeof(OutT) == 4) {
                *(float2*)((float*)C + (size_t)r0 * 1024 + col) =
                    make_float2(c[mt][nt][0], c[mt][nt][1]);
                *(float2*)((float*)C + (size_t)(r0 + 8) * 1024 + col) =
                    make_float2(c[mt][nt][2], c[mt][nt][3]);
            } else {
                *(__half2*)((__half*)C + (size_t)r0 * 1024 + col) =
                    __floats2half2_rn(c[mt][nt][0], c[mt][nt][1]);
                *(__half2*)((__half*)C + (size_t)(r0 + 8) * 1024 + col) =
                    __floats2half2_rn(c[mt][nt][2], c[mt][nt][3]);
            }
        }
    }
}

// ---------------------------------------------------------------------------
// 5) Scan phase 1
// ---------------------------------------------------------------------------
__global__ void scan_partial() {
    int bh = blockIdx.y;
    int ch = blockIdx.x;
    int a = threadIdx.x;
    int b = bh >> 4, h = bh & 15;
    const float* cr = g_cross + bh * N_;
    int n0 = ch * CLEN;
    float sc = 0.f, scv = 0.f;
#pragma unroll 8
    for (int i = 0; i < CLEN; i++) {
        int n = n0 + i;
        float cn = cr[n];
        float v = __half2float(g_valh[((size_t)(b * N_ + n) * H_ + h) * A_ + a]);
        sc += cn;
        scv = fmaf(cn, v, scv);
    }
    g_psum_cv[(bh * NCH + ch) * A_ + a] = scv;
    if (a == 0) g_psum_c[bh * NCH + ch] = sc;
}

// ---------------------------------------------------------------------------
// 6) Scan phase 2: register-resident exclusive prefix
// ---------------------------------------------------------------------------
__global__ void scan_prefix() {
    int bh = blockIdx.x;
    int a = threadIdx.x;
    float r[NCH];
#pragma unroll
    for (int ch = 0; ch < NCH; ch++)
        r[ch] = g_psum_cv[(bh * NCH + ch) * A_ + a];
    float run = 0.f;
#pragma unroll
    for (int ch = 0; ch < NCH; ch++) { float t = r[ch]; r[ch] = run; run += t; }
#pragma unroll
    for (int ch = 0; ch < NCH; ch++)
        g_psum_cv[(bh * NCH + ch) * A_ + a] = r[ch];
    if (a == 0) {
        float rc[NCH];
#pragma unroll
        for (int ch = 0; ch < NCH; ch++) rc[ch] = g_psum_c[bh * NCH + ch];
        float run2 = 0.f;
#pragma unroll
        for (int ch = 0; ch < NCH; ch++) { float t = rc[ch]; rc[ch] = run2; run2 += t; }
#pragma unroll
        for (int ch = 0; ch < NCH; ch++) g_psum_c[bh * NCH + ch] = rc[ch];
    }
}

// ---------------------------------------------------------------------------
// 7) Scan phase 3
// ---------------------------------------------------------------------------
__global__ void scan_final() {
    int bh = blockIdx.y;
    int ch = blockIdx.x;
    int a = threadIdx.x;
    int b = bh >> 4, h = bh & 15;
    float run_cv = g_psum_cv[(bh * NCH + ch) * A_ + a];
    float run_c = g_psum_c[bh * NCH + ch];
    const float* cr = g_cross + bh * N_;
    const float* dg = g_diag + bh * N_;
    const float* ex = g_extra + bh * N_;
    const float* pe = g_p2e + h * N_;
    int n0 = ch * CLEN;
#pragma unroll 8
    for (int i = 0; i < CLEN; i++) {
        int n = n0 + i;
        float cn = cr[n];
        float dn = dg[n];
        float peE = pe[n] * ex[n];
        size_t vidx = ((size_t)(b * N_ + n) * H_ + h) * A_ + a;
        float v = __half2float(g_valh[vidx]);
        run_cv = fmaf(cn, v, run_cv);
        run_c += cn;
        float num = fmaf(run_cv, peE, v * dn);
        float den = fmaf(run_c, peE, dn);
        g_outh[vidx] = __float2half_rn(num / den);
    }
}

// ---------------------------------------------------------------------------
// Launcher
// ---------------------------------------------------------------------------
extern "C" void kernel_launch(void* const* d_in, const int* in_sizes, int n_in,
                              void* d_out, int out_size) {
    const float* x  = (const float*)d_in[0];
    const float* k1 = (const float*)d_in[1];
    const float* k2 = (const float*)d_in[2];
    const float* k3 = (const float*)d_in[3];
    const float* a1 = (const float*)d_in[4];
    const float* a2 = (const float*)d_in[5];
    const float* b1 = (const float*)d_in[6];
    const float* b2 = (const float*)d_in[7];
    const float* cc = (const float*)d_in[8];
    const float* vw = (const float*)d_in[9];
    const float* ow = (const float*)d_in[10];
    float* out = (float*)d_out;

    void *p_wvh, *p_woh, *p_valh, *p_outh, *p_xh;
    cudaGetSymbolAddress(&p_wvh, g_wv_h);
    cudaGetSymbolAddress(&p_woh, g_wo_h);
    cudaGetSymbolAddress(&p_valh, g_valh);
    cudaGetSymbolAddress(&p_outh, g_outh);
    cudaGetSymbolAddress(&p_xh, g_xh);

    cudaFuncSetAttribute(gemm_f16<__half>, cudaFuncAttributeMaxDynamicSharedMemorySize, GSMEM);
    cudaFuncSetAttribute(gemm_f16<float>, cudaFuncAttributeMaxDynamicSharedMemorySize, GSMEM);
    cudaFuncSetAttribute(proj_gemm, cudaFuncAttributeMaxDynamicSharedMemorySize, PSMEM);

    transpose_wv<<<dim3(32, 2, 16), dim3(32, 8)>>>(vw);
    transpose_wo<<<2048, 256>>>(ow);
    pos_kernel<<<(H_ * N_) / 256, 256>>>(a1, a2, b1, b2, cc);
    proj_gemm<<<M_ / PROWS, 512, PSMEM>>>(x, k1, k2, k3);

    // values = x @ Wv^T  -> [b,n,h,a] fp16
    gemm_f16<__half><<<dim3(8, 128), 256, GSMEM>>>((const __half*)p_xh,
                                                   (const __half*)p_wvh,
                                                   (__half*)p_valh);

    scan_partial<<<dim3(NCH, B_ * H_), A_>>>();
    scan_prefix<<<B_ * H_, A_>>>();
    scan_final<<<dim3(NCH, B_ * H_), A_>>>();

    // result = outh @ Wo^T -> d_out (f32)
    gemm_f16<float><<<dim3(8, 128), 256, GSMEM>>>((const __half*)p_outh,
                                                  (const __half*)p_woh, out);
}

// round 8
// speedup vs baseline: 4.8900x; 1.0168x over previous
#include <cuda_runtime.h>
#include <cuda_fp16.h>
#include <math.h>
#include <stdint.h>

// Problem shapes (fixed)
#define B_ 4
#define N_ 4096
#define W_ 1024
#define H_ 16
#define A_ 64
#define HA_ 1024           // H_*A_
#define M_ 16384           // B_*N_
#define NCH 64             // scan chunks per sequence
#define CLEN (N_ / NCH)    // 64 n per chunk

// ---------------------------------------------------------------------------
// Scratch (no allocations allowed -> __device__ globals)
// ---------------------------------------------------------------------------
__device__ __half g_valh[M_ * HA_];         // 32 MB (GEMM1 out, fp16)
__device__ __half g_outh[M_ * HA_];         // 32 MB (GEMM2 in, fp16)
__device__ __half g_xh[M_ * W_];            // fp16 x, 32 MB
__device__ __half g_wv_h[HA_ * W_];         // 2 MB
__device__ __half g_wo_h[W_ * HA_];         // 2 MB
__device__ float g_cross[B_ * H_ * N_];
__device__ float g_diag [B_ * H_ * N_];
__device__ float g_extra[B_ * H_ * N_];
__device__ float g_p1 [H_ * N_];
__device__ float g_p2e[H_ * N_];
__device__ float g_psum_cv[B_ * H_ * NCH * A_];
__device__ float g_psum_c [B_ * H_ * NCH];

__device__ __forceinline__ uint32_t s2u(const void* p) {
    uint32_t r;
    asm("{ .reg .u64 t; cvta.to.shared.u64 t, %1; cvt.u32.u64 %0, t; }" : "=r"(r) : "l"(p));
    return r;
}
__device__ __forceinline__ void cp16(uint32_t dst, const void* src) {
    asm volatile("cp.async.cg.shared.global [%0], [%1], 16;" :: "r"(dst), "l"(src));
}
#define CP_COMMIT() asm volatile("cp.async.commit_group;" ::: "memory")
#define CP_WAIT(n)  asm volatile("cp.async.wait_group %0;" :: "n"(n) : "memory")

// ---------------------------------------------------------------------------
// 1a) Wv transpose, smem tiled, coalesced
// ---------------------------------------------------------------------------
__global__ void transpose_wv(const float* __restrict__ vw) {
    __shared__ float tile[32][33];
    int h = blockIdx.z;
    int w0 = blockIdx.x * 32;
    int a0 = blockIdx.y * 32;
    int tx = threadIdx.x, ty = threadIdx.y;     // 32 x 8
#pragma unroll
    for (int i = 0; i < 4; i++) {
        int w = w0 + ty + i * 8;
        tile[ty + i * 8][tx] = vw[((h << 10) + w) * 64 + a0 + tx];
    }
    __syncthreads();
#pragma unroll
    for (int i = 0; i < 4; i++) {
        int a = a0 + ty + i * 8;
        g_wv_h[((h << 6) + a) * 1024 + w0 + tx] = __float2half_rn(tile[tx][ty + i * 8]);
    }
}

// ---------------------------------------------------------------------------
// 1b) Wo permuted copy
// ---------------------------------------------------------------------------
__global__ void transpose_wo(const float* __restrict__ ow) {
    int i2 = (blockIdx.x * blockDim.x + threadIdx.x) * 2;
    int a = i2 & 63;
    int hq = (i2 >> 6) & 15;
    int w = i2 >> 10;
    float2 v = *(const float2*)(ow + (size_t)(((hq << 10) + w) << 6) + a);
    *(__half2*)(g_wo_h + i2) = __floats2half2_rn(v.x, v.y);
}

// ---------------------------------------------------------------------------
// 2) Positional
// ---------------------------------------------------------------------------
__global__ void pos_kernel(const float* __restrict__ a1, const float* __restrict__ a2,
                           const float* __restrict__ b1, const float* __restrict__ b2,
                           const float* __restrict__ cc) {
    int idx = blockIdx.x * blockDim.x + threadIdx.x;
    int h = idx >> 12;
    int n = idx & (N_ - 1);
    float nv = (float)n * (1.0f / 4095.0f);
    float s1 = 0.f, s2 = 0.f;
#pragma unroll 8
    for (int p = 0; p < 64; p++) {
        float cp = cc[h * 64 + p];
        s1 += sinf(fmaf(a1[h * 64 + p], nv, b1[h * 64 + p])) * cp;
        s2 += sinf(fmaf(a2[h * 64 + p], nv, b2[h * 64 + p])) * cp;
    }
    g_p1[idx] = s1;
    s2 = fminf(fmaxf(s2, -20.f), 20.f);
    g_p2e[idx] = expf(s2);
}

// ---------------------------------------------------------------------------
// 3) Projection GEMM: Z[16384, 48] = x @ [k1|k2|k3]^T, fp32 register tiled.
//    PROWS=64 rows/block, PKC=64, 256 threads, grid 256 (occupancy-oriented).
//    Also writes the fp16 copy of x for GEMM1.
// ---------------------------------------------------------------------------
#define PROWS 64
#define PKC 64
#define XPITCH 68
#define KPITCH 69
#define PSMEM ((PROWS * XPITCH + 48 * KPITCH) * 4)

__global__ __launch_bounds__(256) void proj_gemm(const float* __restrict__ x,
                                                 const float* __restrict__ k1,
                                                 const float* __restrict__ k2,
                                                 const float* __restrict__ k3) {
    extern __shared__ __align__(16) float ps[];
    float* xs = ps;                       // [PROWS][XPITCH]
    float* ks = ps + PROWS * XPITCH;      // [48][KPITCH]

    int tid = threadIdx.x;
    int row0 = blockIdx.x * PROWS;
    int tr = tid >> 3;                    // 0..31 -> rows tr*2, tr*2+1
    int tc = tid & 7;                     // 0..7  -> cols tc*6..tc*6+5

    const float* kmat[3] = {k1, k2, k3};

    float acc[2][6];
#pragma unroll
    for (int i = 0; i < 2; i++)
#pragma unroll
        for (int j = 0; j < 6; j++) acc[i][j] = 0.f;

    for (int k0 = 0; k0 < W_; k0 += PKC) {
        // fill x tile (and fp16 shadow of x): 64x64 floats = 1024 float4
#pragma unroll
        for (int i = 0; i < 4; i++) {
            int f = tid + i * 256;
            int r = f >> 4, c4 = (f & 15) * 4;
            float4 v = *(const float4*)(x + (size_t)(row0 + r) * W_ + k0 + c4);
            *(float4*)(xs + r * XPITCH + c4) = v;
            __half2 h0 = __floats2half2_rn(v.x, v.y);
            __half2 h1 = __floats2half2_rn(v.z, v.w);
            *(uint2*)(g_xh + (size_t)(row0 + r) * W_ + k0 + c4) =
                make_uint2(*(uint32_t*)&h0, *(uint32_t*)&h1);
        }
        // fill k tile: 48x64
#pragma unroll
        for (int i = tid; i < 48 * PKC; i += 256) {
            int j = i >> 6;
            int kk = i & (PKC - 1);
            ks[j * KPITCH + kk] = kmat[j >> 4][(j & 15) * W_ + k0 + kk];
        }
        __syncthreads();

        const float* xp0 = xs + (tr * 2) * XPITCH;
        const float* xp1 = xp0 + XPITCH;
        const float* kp = ks + (tc * 6) * KPITCH;
#pragma unroll 4
        for (int kk = 0; kk < PKC; kk++) {
            float x0 = xp0[kk], x1 = xp1[kk];
            float kv[6];
#pragma unroll
            for (int j = 0; j < 6; j++) kv[j] = kp[j * KPITCH + kk];
#pragma unroll
            for (int j = 0; j < 6; j++) {
                acc[0][j] = fmaf(x0, kv[j], acc[0][j]);
                acc[1][j] = fmaf(x1, kv[j], acc[1][j]);
            }
        }
        __syncthreads();
    }

    // epilogue: add p1 (cross only), clip, exp, scatter to [b,h,n]
#pragma unroll
    for (int i = 0; i < 2; i++) {
        int row = row0 + tr * 2 + i;
        int b = row >> 12, n = row & (N_ - 1);
#pragma unroll
        for (int j = 0; j < 6; j++) {
            int col = tc * 6 + j;
            int which = col >> 4, h = col & 15;
            float s = acc[i][j];
            if (which == 0) s += g_p1[h * N_ + n];
            s = fminf(fmaxf(s, -20.f), 20.f);
            s = expf(s);
            int off = (b * H_ + h) * N_ + n;
            if (which == 0)      g_cross[off] = s;
            else if (which == 1) g_diag[off]  = s;
            else                 g_extra[off] = s;
        }
    }
}

// ---------------------------------------------------------------------------
// 4/7) fp16 mma.m16n8k16 GEMM, cp.async 4-stage pipeline, ldmatrix fragments.
//      All 12 ldmatrix per tile issued before all 32 MMAs (latency overlap).
// ---------------------------------------------------------------------------
#define BK 32
#define KPADH 40
#define KT2 (1024 / BK)
#define STG 4
#define HALF_BYTES (128 * KPADH * 2)
#define STAGE_BYTES (2 * HALF_BYTES)
#define GSMEM (STG * STAGE_BYTES)

__device__ __forceinline__ void mma16816(float* c, const uint32_t* a, const uint32_t* b) {
    asm volatile(
        "mma.sync.aligned.m16n8k16.row.col.f32.f16.f16.f32 "
        "{%0,%1,%2,%3}, {%4,%5,%6,%7}, {%8,%9}, {%0,%1,%2,%3};"
        : "+f"(c[0]), "+f"(c[1]), "+f"(c[2]), "+f"(c[3])
        : "r"(a[0]), "r"(a[1]), "r"(a[2]), "r"(a[3]), "r"(b[0]), "r"(b[1]));
}
__device__ __forceinline__ void ldsm4(uint32_t* r, uint32_t addr) {
    asm volatile("ldmatrix.sync.aligned.m8n8.x4.shared.b16 {%0,%1,%2,%3}, [%4];"
                 : "=r"(r[0]), "=r"(r[1]), "=r"(r[2]), "=r"(r[3]) : "r"(addr));
}

template <typename OutT>
__global__ __launch_bounds__(256, 2) void gemm_f16(const __half* __restrict__ A,
                                                   const __half* __restrict__ Bt,
                                                   OutT* __restrict__ C) {
    extern __shared__ __align__(16) char smem[];
    uint32_t smem_u = s2u(smem);

    int tid = threadIdx.x;
    int lane = tid & 31, wid = tid >> 5;
    int wm = wid >> 2;
    int wn = wid & 3;
    int gid = lane >> 2;
    int tig = lane & 3;
    int lr = lane & 15;
    int lk = (lane >> 4) << 3;

    int bn = blockIdx.x, bm = blockIdx.y;
    const __half* Ag = A + (size_t)(bm * 128) * 1024;
    const __half* Bg = Bt + (size_t)(bn * 128) * 1024;

    int c0row = tid >> 2;
    int c0k = (tid & 3) * 8;

    float c[4][4][4];
#pragma unroll
    for (int i = 0; i < 4; i++)
#pragma unroll
        for (int j = 0; j < 4; j++)
#pragma unroll
            for (int q = 0; q < 4; q++) c[i][j][q] = 0.f;

    auto load_stage = [&](int t, int s) {
        int k0 = t * BK;
        uint32_t base = smem_u + s * STAGE_BYTES;
#pragma unroll
        for (int i = 0; i < 2; i++) {
            int row = c0row + i * 64;
            uint32_t off = (uint32_t)(row * (KPADH * 2) + c0k * 2);
            cp16(base + off, Ag + (size_t)row * 1024 + k0 + c0k);
            cp16(base + HALF_BYTES + off, Bg + (size_t)row * 1024 + k0 + c0k);
        }
    };

#pragma unroll
    for (int s = 0; s < STG - 1; s++) {
        load_stage(s, s);
        CP_COMMIT();
    }

    int buf = 0;
    for (int t = 0; t < KT2; t++) {
        CP_WAIT(STG - 2);
        __syncthreads();
        if (t + STG - 1 < KT2) {
            int nb = buf + (STG - 1);
            if (nb >= STG) nb -= STG;
            load_stage(t + STG - 1, nb);
            CP_COMMIT();
        } else {
            CP_COMMIT();
        }

        uint32_t a_base = smem_u + buf * STAGE_BYTES;
        uint32_t b_base = a_base + HALF_BYTES;

        // preload ALL fragments for both k-groups, then run all MMAs
        uint32_t af[2][4][4], bf[2][4][2];
#pragma unroll
        for (int g = 0; g < 2; g++) {
            int kk = g * 16;
#pragma unroll
            for (int mt = 0; mt < 4; mt++) {
                uint32_t addr = a_base +
                    ((wm * 64 + mt * 16 + lr) * KPADH + kk + lk) * 2;
                ldsm4(af[g][mt], addr);
            }
#pragma unroll
            for (int p = 0; p < 2; p++) {
                uint32_t r[4];
                uint32_t addr = b_base +
                    ((wn * 32 + p * 16 + lr) * KPADH + kk + lk) * 2;
                ldsm4(r, addr);
                bf[g][2 * p][0] = r[0];     bf[g][2 * p][1] = r[2];
                bf[g][2 * p + 1][0] = r[1]; bf[g][2 * p + 1][1] = r[3];
            }
        }
#pragma unroll
        for (int g = 0; g < 2; g++)
#pragma unroll
            for (int mt = 0; mt < 4; mt++)
#pragma unroll
                for (int nt = 0; nt < 4; nt++)
                    mma16816(c[mt][nt], af[g][mt], bf[g][nt]);

        buf = (buf + 1 == STG) ? 0 : buf + 1;
    }

#pragma unroll
    for (int mt = 0; mt < 4; mt++) {
        int r0 = bm * 128 + wm * 64 + mt * 16 + gid;
#pragma unroll
        for (int nt = 0; nt < 4; nt++) {
            int col = bn * 128 + wn * 32 + nt * 8 + tig * 2;
            if (sizeof(OutT) == 4) {
                *(float2*)((float*)C + (size_t)r0 * 1024 + col) =
                    make_float2(c[mt][nt][0], c[mt][nt][1]);
                *(float2*)((float*)C + (size_t)(r0 + 8) * 1024 + col) =
                    make_float2(c[mt][nt][2], c[mt][nt][3]);
            } else {
                *(__half2*)((__half*)C + (size_t)r0 * 1024 + col) =
                    __floats2half2_rn(c[mt][nt][0], c[mt][nt][1]);
                *(__half2*)((__half*)C + (size_t)(r0 + 8) * 1024 + col) =
                    __floats2half2_rn(c[mt][nt][2], c[mt][nt][3]);
            }
        }
    }
}

// ---------------------------------------------------------------------------
// 5) Scan phase 1
// ---------------------------------------------------------------------------
__global__ void scan_partial() {
    int bh = blockIdx.y;
    int ch = blockIdx.x;
    int a = threadIdx.x;
    int b = bh >> 4, h = bh & 15;
    const float* cr = g_cross + bh * N_;
    int n0 = ch * CLEN;
    float sc = 0.f, scv = 0.f;
#pragma unroll 8
    for (int i = 0; i < CLEN; i++) {
        int n = n0 + i;
        float cn = cr[n];
        float v = __half2float(g_valh[((size_t)(b * N_ + n) * H_ + h) * A_ + a]);
        sc += cn;
        scv = fmaf(cn, v, scv);
    }
    g_psum_cv[(bh * NCH + ch) * A_ + a] = scv;
    if (a == 0) g_psum_c[bh * NCH + ch] = sc;
}

// ---------------------------------------------------------------------------
// 6) Scan phase 2: register-resident exclusive prefix
// ---------------------------------------------------------------------------
__global__ void scan_prefix() {
    int bh = blockIdx.x;
    int a = threadIdx.x;
    float r[NCH];
#pragma unroll
    for (int ch = 0; ch < NCH; ch++)
        r[ch] = g_psum_cv[(bh * NCH + ch) * A_ + a];
    float run = 0.f;
#pragma unroll
    for (int ch = 0; ch < NCH; ch++) { float t = r[ch]; r[ch] = run; run += t; }
#pragma unroll
    for (int ch = 0; ch < NCH; ch++)
        g_psum_cv[(bh * NCH + ch) * A_ + a] = r[ch];
    if (a == 0) {
        float rc[NCH];
#pragma unroll
        for (int ch = 0; ch < NCH; ch++) rc[ch] = g_psum_c[bh * NCH + ch];
        float run2 = 0.f;
#pragma unroll
        for (int ch = 0; ch < NCH; ch++) { float t = rc[ch]; rc[ch] = run2; run2 += t; }
#pragma unroll
        for (int ch = 0; ch < NCH; ch++) g_psum_c[bh * NCH + ch] = rc[ch];
    }
}

// ---------------------------------------------------------------------------
// 7) Scan phase 3
// ---------------------------------------------------------------------------
__global__ void scan_final() {
    int bh = blockIdx.y;
    int ch = blockIdx.x;
    int a = threadIdx.x;
    int b = bh >> 4, h = bh & 15;
    float run_cv = g_psum_cv[(bh * NCH + ch) * A_ + a];
    float run_c = g_psum_c[bh * NCH + ch];
    const float* cr = g_cross + bh * N_;
    const float* dg = g_diag + bh * N_;
    const float* ex = g_extra + bh * N_;
    const float* pe = g_p2e + h * N_;
    int n0 = ch * CLEN;
#pragma unroll 8
    for (int i = 0; i < CLEN; i++) {
        int n = n0 + i;
        float cn = cr[n];
        float dn = dg[n];
        float peE = pe[n] * ex[n];
        size_t vidx = ((size_t)(b * N_ + n) * H_ + h) * A_ + a;
        float v = __half2float(g_valh[vidx]);
        run_cv = fmaf(cn, v, run_cv);
        run_c += cn;
        float num = fmaf(run_cv, peE, v * dn);
        float den = fmaf(run_c, peE, dn);
        g_outh[vidx] = __float2half_rn(num / den);
    }
}

// ---------------------------------------------------------------------------
// Launcher
// ---------------------------------------------------------------------------
extern "C" void kernel_launch(void* const* d_in, const int* in_sizes, int n_in,
                              void* d_out, int out_size) {
    const float* x  = (const float*)d_in[0];
    const float* k1 = (const float*)d_in[1];
    const float* k2 = (const float*)d_in[2];
    const float* k3 = (const float*)d_in[3];
    const float* a1 = (const float*)d_in[4];
    const float* a2 = (const float*)d_in[5];
    const float* b1 = (const float*)d_in[6];
    const float* b2 = (const float*)d_in[7];
    const float* cc = (const float*)d_in[8];
    const float* vw = (const float*)d_in[9];
    const float* ow = (const float*)d_in[10];
    float* out = (float*)d_out;

    void *p_wvh, *p_woh, *p_valh, *p_outh, *p_xh;
    cudaGetSymbolAddress(&p_wvh, g_wv_h);
    cudaGetSymbolAddress(&p_woh, g_wo_h);
    cudaGetSymbolAddress(&p_valh, g_valh);
    cudaGetSymbolAddress(&p_outh, g_outh);
    cudaGetSymbolAddress(&p_xh, g_xh);

    cudaFuncSetAttribute(gemm_f16<__half>, cudaFuncAttributeMaxDynamicSharedMemorySize, GSMEM);
    cudaFuncSetAttribute(gemm_f16<float>, cudaFuncAttributeMaxDynamicSharedMemorySize, GSMEM);
    cudaFuncSetAttribute(proj_gemm, cudaFuncAttributeMaxDynamicSharedMemorySize, PSMEM);

    transpose_wv<<<dim3(32, 2, 16), dim3(32, 8)>>>(vw);
    transpose_wo<<<2048, 256>>>(ow);
    pos_kernel<<<(H_ * N_) / 256, 256>>>(a1, a2, b1, b2, cc);
    proj_gemm<<<M_ / PROWS, 256, PSMEM>>>(x, k1, k2, k3);

    // values = x @ Wv^T  -> [b,n,h,a] fp16
    gemm_f16<__half><<<dim3(8, 128), 256, GSMEM>>>((const __half*)p_xh,
                                                   (const __half*)p_wvh,
                                                   (__half*)p_valh);

    scan_partial<<<dim3(NCH, B_ * H_), A_>>>();
    scan_prefix<<<B_ * H_, A_>>>();
    scan_final<<<dim3(NCH, B_ * H_), A_>>>();

    // result = outh @ Wo^T -> d_out (f32)
    gemm_f16<float><<<dim3(8, 128), 256, GSMEM>>>((const __half*)p_outh,
                                                  (const __half*)p_woh, out);
}

// round 9
// speedup vs baseline: 5.6279x; 1.1509x over previous
#include <cuda_runtime.h>
#include <cuda_fp16.h>
#include <math.h>
#include <stdint.h>

// Problem shapes (fixed)
#define B_ 4
#define N_ 4096
#define W_ 1024
#define H_ 16
#define A_ 64
#define HA_ 1024           // H_*A_
#define M_ 16384           // B_*N_
#define NCH 64             // scan chunks per sequence
#define CLEN (N_ / NCH)    // 64 n per chunk
#define NB1 1152           // GEMM1 extended N (1024 values + 48 proj + 80 pad)

// ---------------------------------------------------------------------------
// Scratch (no allocations allowed -> __device__ globals)
// ---------------------------------------------------------------------------
__device__ __half g_valh[M_ * HA_];         // 32 MB (GEMM1 out, fp16)
__device__ __half g_outh[M_ * HA_];         // 32 MB (GEMM2 in, fp16)
__device__ __half g_xh[M_ * W_];            // fp16 x, 32 MB
__device__ __half g_wv_e[NB1 * W_];         // extended GEMM1 B: 2.25 MB
__device__ __half g_wo_h[W_ * HA_];         // 2 MB
__device__ float g_cross[B_ * H_ * N_];
__device__ float g_diag [B_ * H_ * N_];
__device__ float g_extra[B_ * H_ * N_];
__device__ float g_p1 [H_ * N_];
__device__ float g_p2e[H_ * N_];
__device__ float g_psum_cv[B_ * H_ * NCH * A_];
__device__ float g_psum_c [B_ * H_ * NCH];

__device__ __forceinline__ uint32_t s2u(const void* p) {
    uint32_t r;
    asm("{ .reg .u64 t; cvta.to.shared.u64 t, %1; cvt.u32.u64 %0, t; }" : "=r"(r) : "l"(p));
    return r;
}
__device__ __forceinline__ void cp16(uint32_t dst, const void* src) {
    asm volatile("cp.async.cg.shared.global [%0], [%1], 16;" :: "r"(dst), "l"(src));
}
#define CP_COMMIT() asm volatile("cp.async.commit_group;" ::: "memory")
#define CP_WAIT(n)  asm volatile("cp.async.wait_group %0;" :: "n"(n) : "memory")

// ---------------------------------------------------------------------------
// 0) x -> fp16 convert (feeds GEMM1 A)
// ---------------------------------------------------------------------------
__global__ void convert_x(const float* __restrict__ x) {
    size_t i = ((size_t)blockIdx.x * blockDim.x + threadIdx.x) * 8;
    float4 v1 = *(const float4*)(x + i);
    float4 v2 = *(const float4*)(x + i + 4);
    __half2 h0 = __floats2half2_rn(v1.x, v1.y);
    __half2 h1 = __floats2half2_rn(v1.z, v1.w);
    __half2 h2 = __floats2half2_rn(v2.x, v2.y);
    __half2 h3 = __floats2half2_rn(v2.z, v2.w);
    *(uint4*)(g_xh + i) = make_uint4(*(uint32_t*)&h0, *(uint32_t*)&h1,
                                     *(uint32_t*)&h2, *(uint32_t*)&h3);
}

// ---------------------------------------------------------------------------
// 1a) Wv transpose into extended B rows 0..1023, smem tiled, coalesced
// ---------------------------------------------------------------------------
__global__ void transpose_wv(const float* __restrict__ vw) {
    __shared__ float tile[32][33];
    int h = blockIdx.z;
    int w0 = blockIdx.x * 32;
    int a0 = blockIdx.y * 32;
    int tx = threadIdx.x, ty = threadIdx.y;     // 32 x 8
#pragma unroll
    for (int i = 0; i < 4; i++) {
        int w = w0 + ty + i * 8;
        tile[ty + i * 8][tx] = vw[((h << 10) + w) * 64 + a0 + tx];
    }
    __syncthreads();
#pragma unroll
    for (int i = 0; i < 4; i++) {
        int a = a0 + ty + i * 8;
        g_wv_e[((h << 6) + a) * 1024 + w0 + tx] = __float2half_rn(tile[tx][ty + i * 8]);
    }
}

// ---------------------------------------------------------------------------
// 1c) Extended B rows 1024..1151: k1/k2/k3 heads then zero pad
// ---------------------------------------------------------------------------
__global__ void fill_proj_rows(const float* __restrict__ k1,
                               const float* __restrict__ k2,
                               const float* __restrict__ k3) {
    int idx = blockIdx.x * blockDim.x + threadIdx.x;   // 0..128*1024-1
    int j = idx >> 10;          // 0..127 (row - 1024)
    int w = idx & 1023;
    __half v = __float2half(0.f);
    if (j < 48) {
        const float* kk = (j < 16) ? k1 : ((j < 32) ? k2 : k3);
        v = __float2half_rn(kk[(j & 15) * W_ + w]);
    }
    g_wv_e[(size_t)(1024 + j) * 1024 + w] = v;
}

// ---------------------------------------------------------------------------
// 1b) Wo permuted copy
// ---------------------------------------------------------------------------
__global__ void transpose_wo(const float* __restrict__ ow) {
    int i2 = (blockIdx.x * blockDim.x + threadIdx.x) * 2;
    int a = i2 & 63;
    int hq = (i2 >> 6) & 15;
    int w = i2 >> 10;
    float2 v = *(const float2*)(ow + (size_t)(((hq << 10) + w) << 6) + a);
    *(__half2*)(g_wo_h + i2) = __floats2half2_rn(v.x, v.y);
}

// ---------------------------------------------------------------------------
// 2) Positional
// ---------------------------------------------------------------------------
__global__ void pos_kernel(const float* __restrict__ a1, const float* __restrict__ a2,
                           const float* __restrict__ b1, const float* __restrict__ b2,
                           const float* __restrict__ cc) {
    int idx = blockIdx.x * blockDim.x + threadIdx.x;
    int h = idx >> 12;
    int n = idx & (N_ - 1);
    float nv = (float)n * (1.0f / 4095.0f);
    float s1 = 0.f, s2 = 0.f;
#pragma unroll 8
    for (int p = 0; p < 64; p++) {
        float cp = cc[h * 64 + p];
        s1 += sinf(fmaf(a1[h * 64 + p], nv, b1[h * 64 + p])) * cp;
        s2 += sinf(fmaf(a2[h * 64 + p], nv, b2[h * 64 + p])) * cp;
    }
    g_p1[idx] = s1;
    s2 = fminf(fmaxf(s2, -20.f), 20.f);
    g_p2e[idx] = expf(s2);
}

// ---------------------------------------------------------------------------
// 4/7) fp16 mma.m16n8k16 GEMM, cp.async 4-stage pipeline.
//      EPI: 0 = half C, 1 = float C, 2 = half C + fused proj tile at bn==8
// ---------------------------------------------------------------------------
#define BK 32
#define KPADH 40
#define KT2 (1024 / BK)
#define STG 4
#define HALF_BYTES (128 * KPADH * 2)
#define STAGE_BYTES (2 * HALF_BYTES)
#define GSMEM (STG * STAGE_BYTES)

__device__ __forceinline__ void mma16816(float* c, const uint32_t* a, const uint32_t* b) {
    asm volatile(
        "mma.sync.aligned.m16n8k16.row.col.f32.f16.f16.f32 "
        "{%0,%1,%2,%3}, {%4,%5,%6,%7}, {%8,%9}, {%0,%1,%2,%3};"
        : "+f"(c[0]), "+f"(c[1]), "+f"(c[2]), "+f"(c[3])
        : "r"(a[0]), "r"(a[1]), "r"(a[2]), "r"(a[3]), "r"(b[0]), "r"(b[1]));
}
__device__ __forceinline__ void ldsm4(uint32_t* r, uint32_t addr) {
    asm volatile("ldmatrix.sync.aligned.m8n8.x4.shared.b16 {%0,%1,%2,%3}, [%4];"
                 : "=r"(r[0]), "=r"(r[1]), "=r"(r[2]), "=r"(r[3]) : "r"(addr));
}

__device__ __forceinline__ void proj_store(float s, int which, int h, int b, int n) {
    s = fminf(fmaxf(s, -20.f), 20.f);
    s = expf(s);
    int off = (b * H_ + h) * N_ + n;
    if (which == 0)      g_cross[off] = s;
    else if (which == 1) g_diag[off]  = s;
    else                 g_extra[off] = s;
}

template <int EPI>
__global__ __launch_bounds__(256, 2) void gemm_f16(const __half* __restrict__ A,
                                                   const __half* __restrict__ Bt,
                                                   void* __restrict__ Cv) {
    extern __shared__ __align__(16) char smem[];
    uint32_t smem_u = s2u(smem);

    int tid = threadIdx.x;
    int lane = tid & 31, wid = tid >> 5;
    int wm = wid >> 2;
    int wn = wid & 3;
    int gid = lane >> 2;
    int tig = lane & 3;
    int lr = lane & 15;
    int lk = (lane >> 4) << 3;

    int bn = blockIdx.x, bm = blockIdx.y;
    const __half* Ag = A + (size_t)(bm * 128) * 1024;
    const __half* Bg = Bt + (size_t)(bn * 128) * 1024;

    int c0row = tid >> 2;
    int c0k = (tid & 3) * 8;

    float c[4][4][4];
#pragma unroll
    for (int i = 0; i < 4; i++)
#pragma unroll
        for (int j = 0; j < 4; j++)
#pragma unroll
            for (int q = 0; q < 4; q++) c[i][j][q] = 0.f;

    auto load_stage = [&](int t, int s) {
        int k0 = t * BK;
        uint32_t base = smem_u + s * STAGE_BYTES;
#pragma unroll
        for (int i = 0; i < 2; i++) {
            int row = c0row + i * 64;
            uint32_t off = (uint32_t)(row * (KPADH * 2) + c0k * 2);
            cp16(base + off, Ag + (size_t)row * 1024 + k0 + c0k);
            cp16(base + HALF_BYTES + off, Bg + (size_t)row * 1024 + k0 + c0k);
        }
    };

#pragma unroll
    for (int s = 0; s < STG - 1; s++) {
        load_stage(s, s);
        CP_COMMIT();
    }

    int buf = 0;
    for (int t = 0; t < KT2; t++) {
        CP_WAIT(STG - 2);
        __syncthreads();
        if (t + STG - 1 < KT2) {
            int nb = buf + (STG - 1);
            if (nb >= STG) nb -= STG;
            load_stage(t + STG - 1, nb);
            CP_COMMIT();
        } else {
            CP_COMMIT();
        }

        uint32_t a_base = smem_u + buf * STAGE_BYTES;
        uint32_t b_base = a_base + HALF_BYTES;
#pragma unroll
        for (int g = 0; g < 2; g++) {
            int kk = g * 16;
            uint32_t af[4][4], bf[4][2];
#pragma unroll
            for (int mt = 0; mt < 4; mt++) {
                uint32_t addr = a_base +
                    ((wm * 64 + mt * 16 + lr) * KPADH + kk + lk) * 2;
                ldsm4(af[mt], addr);
            }
#pragma unroll
            for (int p = 0; p < 2; p++) {
                uint32_t r[4];
                uint32_t addr = b_base +
                    ((wn * 32 + p * 16 + lr) * KPADH + kk + lk) * 2;
                ldsm4(r, addr);
                bf[2 * p][0] = r[0];     bf[2 * p][1] = r[2];
                bf[2 * p + 1][0] = r[1]; bf[2 * p + 1][1] = r[3];
            }
#pragma unroll
            for (int mt = 0; mt < 4; mt++)
#pragma unroll
                for (int nt = 0; nt < 4; nt++)
                    mma16816(c[mt][nt], af[mt], bf[nt]);
        }
        buf = (buf + 1 == STG) ? 0 : buf + 1;
    }

    // ---------------- epilogue ----------------
    if (EPI == 2 && bn == 8) {
        // fused projection tile: cols 0..47 of this tile are z-values.
#pragma unroll
        for (int mt = 0; mt < 4; mt++) {
            int r0 = bm * 128 + wm * 64 + mt * 16 + gid;
            int b0 = r0 >> 12, n0 = r0 & (N_ - 1);
            int r1 = r0 + 8;
            int b1v = r1 >> 12, n1 = r1 & (N_ - 1);
#pragma unroll
            for (int nt = 0; nt < 4; nt++) {
                int col = wn * 32 + nt * 8 + tig * 2;
                if (col < 48) {
#pragma unroll
                    for (int q = 0; q < 2; q++) {
                        int cl = col + q;
                        int which = cl >> 4, h = cl & 15;
                        float p1a = (which == 0) ? g_p1[h * N_ + n0] : 0.f;
                        float p1b = (which == 0) ? g_p1[h * N_ + n1] : 0.f;
                        proj_store(c[mt][nt][q] + p1a, which, h, b0, n0);
                        proj_store(c[mt][nt][2 + q] + p1b, which, h, b1v, n1);
                    }
                }
            }
        }
        return;
    }

#pragma unroll
    for (int mt = 0; mt < 4; mt++) {
        int r0 = bm * 128 + wm * 64 + mt * 16 + gid;
#pragma unroll
        for (int nt = 0; nt < 4; nt++) {
            int col = bn * 128 + wn * 32 + nt * 8 + tig * 2;
            if (EPI == 1) {
                *(float2*)((float*)Cv + (size_t)r0 * 1024 + col) =
                    make_float2(c[mt][nt][0], c[mt][nt][1]);
                *(float2*)((float*)Cv + (size_t)(r0 + 8) * 1024 + col) =
                    make_float2(c[mt][nt][2], c[mt][nt][3]);
            } else {
                *(__half2*)((__half*)Cv + (size_t)r0 * 1024 + col) =
                    __floats2half2_rn(c[mt][nt][0], c[mt][nt][1]);
                *(__half2*)((__half*)Cv + (size_t)(r0 + 8) * 1024 + col) =
                    __floats2half2_rn(c[mt][nt][2], c[mt][nt][3]);
            }
        }
    }
}

// ---------------------------------------------------------------------------
// 5) Scan phase 1
// ---------------------------------------------------------------------------
__global__ void scan_partial() {
    int bh = blockIdx.y;
    int ch = blockIdx.x;
    int a = threadIdx.x;
    int b = bh >> 4, h = bh & 15;
    const float* cr = g_cross + bh * N_;
    int n0 = ch * CLEN;
    float sc = 0.f, scv = 0.f;
#pragma unroll 8
    for (int i = 0; i < CLEN; i++) {
        int n = n0 + i;
        float cn = cr[n];
        float v = __half2float(g_valh[((size_t)(b * N_ + n) * H_ + h) * A_ + a]);
        sc += cn;
        scv = fmaf(cn, v, scv);
    }
    g_psum_cv[(bh * NCH + ch) * A_ + a] = scv;
    if (a == 0) g_psum_c[bh * NCH + ch] = sc;
}

// ---------------------------------------------------------------------------
// 6) Scan phase 2: register-resident exclusive prefix
// ---------------------------------------------------------------------------
__global__ void scan_prefix() {
    int bh = blockIdx.x;
    int a = threadIdx.x;
    float r[NCH];
#pragma unroll
    for (int ch = 0; ch < NCH; ch++)
        r[ch] = g_psum_cv[(bh * NCH + ch) * A_ + a];
    float run = 0.f;
#pragma unroll
    for (int ch = 0; ch < NCH; ch++) { float t = r[ch]; r[ch] = run; run += t; }
#pragma unroll
    for (int ch = 0; ch < NCH; ch++)
        g_psum_cv[(bh * NCH + ch) * A_ + a] = r[ch];
    if (a == 0) {
        float rc[NCH];
#pragma unroll
        for (int ch = 0; ch < NCH; ch++) rc[ch] = g_psum_c[bh * NCH + ch];
        float run2 = 0.f;
#pragma unroll
        for (int ch = 0; ch < NCH; ch++) { float t = rc[ch]; rc[ch] = run2; run2 += t; }
#pragma unroll
        for (int ch = 0; ch < NCH; ch++) g_psum_c[bh * NCH + ch] = rc[ch];
    }
}

// ---------------------------------------------------------------------------
// 7) Scan phase 3
// ---------------------------------------------------------------------------
__global__ void scan_final() {
    int bh = blockIdx.y;
    int ch = blockIdx.x;
    int a = threadIdx.x;
    int b = bh >> 4, h = bh & 15;
    float run_cv = g_psum_cv[(bh * NCH + ch) * A_ + a];
    float run_c = g_psum_c[bh * NCH + ch];
    const float* cr = g_cross + bh * N_;
    const float* dg = g_diag + bh * N_;
    const float* ex = g_extra + bh * N_;
    const float* pe = g_p2e + h * N_;
    int n0 = ch * CLEN;
#pragma unroll 8
    for (int i = 0; i < CLEN; i++) {
        int n = n0 + i;
        float cn = cr[n];
        float dn = dg[n];
        float peE = pe[n] * ex[n];
        size_t vidx = ((size_t)(b * N_ + n) * H_ + h) * A_ + a;
        float v = __half2float(g_valh[vidx]);
        run_cv = fmaf(cn, v, run_cv);
        run_c += cn;
        float num = fmaf(run_cv, peE, v * dn);
        float den = fmaf(run_c, peE, dn);
        g_outh[vidx] = __float2half_rn(num / den);
    }
}

// ---------------------------------------------------------------------------
// Launcher
// ---------------------------------------------------------------------------
extern "C" void kernel_launch(void* const* d_in, const int* in_sizes, int n_in,
                              void* d_out, int out_size) {
    const float* x  = (const float*)d_in[0];
    const float* k1 = (const float*)d_in[1];
    const float* k2 = (const float*)d_in[2];
    const float* k3 = (const float*)d_in[3];
    const float* a1 = (const float*)d_in[4];
    const float* a2 = (const float*)d_in[5];
    const float* b1 = (const float*)d_in[6];
    const float* b2 = (const float*)d_in[7];
    const float* cc = (const float*)d_in[8];
    const float* vw = (const float*)d_in[9];
    const float* ow = (const float*)d_in[10];
    float* out = (float*)d_out;

    void *p_wve, *p_woh, *p_valh, *p_outh, *p_xh;
    cudaGetSymbolAddress(&p_wve, g_wv_e);
    cudaGetSymbolAddress(&p_woh, g_wo_h);
    cudaGetSymbolAddress(&p_valh, g_valh);
    cudaGetSymbolAddress(&p_outh, g_outh);
    cudaGetSymbolAddress(&p_xh, g_xh);

    cudaFuncSetAttribute(gemm_f16<2>, cudaFuncAttributeMaxDynamicSharedMemorySize, GSMEM);
    cudaFuncSetAttribute(gemm_f16<1>, cudaFuncAttributeMaxDynamicSharedMemorySize, GSMEM);

    convert_x<<<M_ * W_ / (256 * 8), 256>>>(x);
    transpose_wv<<<dim3(32, 2, 16), dim3(32, 8)>>>(vw);
    fill_proj_rows<<<512, 256>>>(k1, k2, k3);
    transpose_wo<<<2048, 256>>>(ow);
    pos_kernel<<<(H_ * N_) / 256, 256>>>(a1, a2, b1, b2, cc);

    // GEMM1 (fused proj): values cols 0..1023 -> g_valh; tile bn==8 -> exp scatter
    gemm_f16<2><<<dim3(9, 128), 256, GSMEM>>>((const __half*)p_xh,
                                              (const __half*)p_wve, p_valh);

    scan_partial<<<dim3(NCH, B_ * H_), A_>>>();
    scan_prefix<<<B_ * H_, A_>>>();
    scan_final<<<dim3(NCH, B_ * H_), A_>>>();

    // result = outh @ Wo^T -> d_out (f32)
    gemm_f16<1><<<dim3(8, 128), 256, GSMEM>>>((const __half*)p_outh,
                                              (const __half*)p_woh, out);
}

// round 11
// speedup vs baseline: 6.2741x; 1.1148x over previous
#include <cuda_runtime.h>
#include <cuda_fp16.h>
#include <math.h>
#include <stdint.h>

// Problem shapes (fixed)
#define B_ 4
#define N_ 4096
#define W_ 1024
#define H_ 16
#define A_ 64
#define HA_ 1024           // H_*A_
#define M_ 16384           // B_*N_
#define NB1 1152           // GEMM1 extended N (1024 values + 48 proj + 80 pad)

// ---------------------------------------------------------------------------
// Scratch (no allocations allowed -> __device__ globals)
// ---------------------------------------------------------------------------
__device__ __half g_valh[M_ * HA_];         // 32 MB (GEMM1 out, fp16)
__device__ __half g_outh[M_ * HA_];         // 32 MB (GEMM2 in, fp16)
__device__ __half g_xh[M_ * W_];            // fp16 x, 32 MB
__device__ __half g_wv_e[NB1 * W_];         // extended GEMM1 B: 2.25 MB
__device__ __half g_wo_h[W_ * HA_];         // 2 MB
__device__ float g_cross[B_ * H_ * N_];
__device__ float g_diag [B_ * H_ * N_];
__device__ float g_extra[B_ * H_ * N_];
__device__ float g_p1 [H_ * N_];
__device__ float g_p2e[H_ * N_];

__device__ __forceinline__ uint32_t s2u(const void* p) {
    uint32_t r;
    asm("{ .reg .u64 t; cvta.to.shared.u64 t, %1; cvt.u32.u64 %0, t; }" : "=r"(r) : "l"(p));
    return r;
}
__device__ __forceinline__ void cp16(uint32_t dst, const void* src) {
    asm volatile("cp.async.cg.shared.global [%0], [%1], 16;" :: "r"(dst), "l"(src));
}
#define CP_COMMIT() asm volatile("cp.async.commit_group;" ::: "memory")
#define CP_WAIT(n)  asm volatile("cp.async.wait_group %0;" :: "n"(n) : "memory")

// ---------------------------------------------------------------------------
// 0) x -> fp16 convert (feeds GEMM1 A)
// ---------------------------------------------------------------------------
__global__ void convert_x(const float* __restrict__ x) {
    size_t i = ((size_t)blockIdx.x * blockDim.x + threadIdx.x) * 8;
    float4 v1 = *(const float4*)(x + i);
    float4 v2 = *(const float4*)(x + i + 4);
    __half2 h0 = __floats2half2_rn(v1.x, v1.y);
    __half2 h1 = __floats2half2_rn(v1.z, v1.w);
    __half2 h2 = __floats2half2_rn(v2.x, v2.y);
    __half2 h3 = __floats2half2_rn(v2.z, v2.w);
    *(uint4*)(g_xh + i) = make_uint4(*(uint32_t*)&h0, *(uint32_t*)&h1,
                                     *(uint32_t*)&h2, *(uint32_t*)&h3);
}

// ---------------------------------------------------------------------------
// 1a) Wv transpose into extended B rows 0..1023, smem tiled, coalesced
// ---------------------------------------------------------------------------
__global__ void transpose_wv(const float* __restrict__ vw) {
    __shared__ float tile[32][33];
    int h = blockIdx.z;
    int w0 = blockIdx.x * 32;
    int a0 = blockIdx.y * 32;
    int tx = threadIdx.x, ty = threadIdx.y;     // 32 x 8
#pragma unroll
    for (int i = 0; i < 4; i++) {
        int w = w0 + ty + i * 8;
        tile[ty + i * 8][tx] = vw[((h << 10) + w) * 64 + a0 + tx];
    }
    __syncthreads();
#pragma unroll
    for (int i = 0; i < 4; i++) {
        int a = a0 + ty + i * 8;
        g_wv_e[((h << 6) + a) * 1024 + w0 + tx] = __float2half_rn(tile[tx][ty + i * 8]);
    }
}

// ---------------------------------------------------------------------------
// 1c) Extended B rows 1024..1151: k1/k2/k3 heads then zero pad
// ---------------------------------------------------------------------------
__global__ void fill_proj_rows(const float* __restrict__ k1,
                               const float* __restrict__ k2,
                               const float* __restrict__ k3) {
    int idx = blockIdx.x * blockDim.x + threadIdx.x;
    int j = idx >> 10;          // 0..127 (row - 1024)
    int w = idx & 1023;
    __half v = __float2half(0.f);
    if (j < 48) {
        const float* kk = (j < 16) ? k1 : ((j < 32) ? k2 : k3);
        v = __float2half_rn(kk[(j & 15) * W_ + w]);
    }
    g_wv_e[(size_t)(1024 + j) * 1024 + w] = v;
}

// ---------------------------------------------------------------------------
// 1b) Wo permuted copy
// ---------------------------------------------------------------------------
__global__ void transpose_wo(const float* __restrict__ ow) {
    int i2 = (blockIdx.x * blockDim.x + threadIdx.x) * 2;
    int a = i2 & 63;
    int hq = (i2 >> 6) & 15;
    int w = i2 >> 10;
    float2 v = *(const float2*)(ow + (size_t)(((hq << 10) + w) << 6) + a);
    *(__half2*)(g_wo_h + i2) = __floats2half2_rn(v.x, v.y);
}

// ---------------------------------------------------------------------------
// 2) Positional
// ---------------------------------------------------------------------------
__global__ void pos_kernel(const float* __restrict__ a1, const float* __restrict__ a2,
                           const float* __restrict__ b1, const float* __restrict__ b2,
                           const float* __restrict__ cc) {
    int idx = blockIdx.x * blockDim.x + threadIdx.x;
    int h = idx >> 12;
    int n = idx & (N_ - 1);
    float nv = (float)n * (1.0f / 4095.0f);
    float s1 = 0.f, s2 = 0.f;
#pragma unroll 8
    for (int p = 0; p < 64; p++) {
        float cp = cc[h * 64 + p];
        s1 += sinf(fmaf(a1[h * 64 + p], nv, b1[h * 64 + p])) * cp;
        s2 += sinf(fmaf(a2[h * 64 + p], nv, b2[h * 64 + p])) * cp;
    }
    g_p1[idx] = s1;
    s2 = fminf(fmaxf(s2, -20.f), 20.f);
    g_p2e[idx] = expf(s2);
}

// ---------------------------------------------------------------------------
// 4/7) fp16 mma.m16n8k16 GEMM, cp.async 4-stage pipeline.
//      Fragment prefetch happens AFTER __syncthreads (cp.async completion is
//      per-thread; cross-thread visibility requires the barrier).
//      EPI: 1 = float C, 2 = half C + fused proj tile at bn==8
// ---------------------------------------------------------------------------
#define BK 32
#define KPADH 40
#define KT2 (1024 / BK)
#define STG 4
#define HALF_BYTES (128 * KPADH * 2)
#define STAGE_BYTES (2 * HALF_BYTES)
#define GSMEM (STG * STAGE_BYTES)

__device__ __forceinline__ void mma16816(float* c, const uint32_t* a, const uint32_t* b) {
    asm volatile(
        "mma.sync.aligned.m16n8k16.row.col.f32.f16.f16.f32 "
        "{%0,%1,%2,%3}, {%4,%5,%6,%7}, {%8,%9}, {%0,%1,%2,%3};"
        : "+f"(c[0]), "+f"(c[1]), "+f"(c[2]), "+f"(c[3])
        : "r"(a[0]), "r"(a[1]), "r"(a[2]), "r"(a[3]), "r"(b[0]), "r"(b[1]));
}
__device__ __forceinline__ void ldsm4(uint32_t* r, uint32_t addr) {
    asm volatile("ldmatrix.sync.aligned.m8n8.x4.shared.b16 {%0,%1,%2,%3}, [%4];"
                 : "=r"(r[0]), "=r"(r[1]), "=r"(r[2]), "=r"(r[3]) : "r"(addr));
}

__device__ __forceinline__ void proj_store(float s, int which, int h, int b, int n) {
    s = fminf(fmaxf(s, -20.f), 20.f);
    s = expf(s);
    int off = (b * H_ + h) * N_ + n;
    if (which == 0)      g_cross[off] = s;
    else if (which == 1) g_diag[off]  = s;
    else                 g_extra[off] = s;
}

template <int EPI>
__global__ __launch_bounds__(256, 2) void gemm_f16(const __half* __restrict__ A,
                                                   const __half* __restrict__ Bt,
                                                   void* __restrict__ Cv) {
    extern __shared__ __align__(16) char smem[];
    uint32_t smem_u = s2u(smem);

    int tid = threadIdx.x;
    int lane = tid & 31, wid = tid >> 5;
    int wm = wid >> 2;
    int wn = wid & 3;
    int gid = lane >> 2;
    int tig = lane & 3;
    int lr = lane & 15;
    int lk = (lane >> 4) << 3;

    int bn = blockIdx.x, bm = blockIdx.y;
    const __half* Ag = A + (size_t)(bm * 128) * 1024;
    const __half* Bg = Bt + (size_t)(bn * 128) * 1024;

    int c0row = tid >> 2;
    int c0k = (tid & 3) * 8;

    float c[4][4][4];
#pragma unroll
    for (int i = 0; i < 4; i++)
#pragma unroll
        for (int j = 0; j < 4; j++)
#pragma unroll
            for (int q = 0; q < 4; q++) c[i][j][q] = 0.f;

    auto load_stage = [&](int t, int s) {
        int k0 = t * BK;
        uint32_t base = smem_u + s * STAGE_BYTES;
#pragma unroll
        for (int i = 0; i < 2; i++) {
            int row = c0row + i * 64;
            uint32_t off = (uint32_t)(row * (KPADH * 2) + c0k * 2);
            cp16(base + off, Ag + (size_t)row * 1024 + k0 + c0k);
            cp16(base + HALF_BYTES + off, Bg + (size_t)row * 1024 + k0 + c0k);
        }
    };
    auto ldsm_group = [&](uint32_t af[4][4], uint32_t bf[4][2],
                          uint32_t a_base, int kk) {
        uint32_t b_base = a_base + HALF_BYTES;
#pragma unroll
        for (int mt = 0; mt < 4; mt++) {
            uint32_t addr = a_base + ((wm * 64 + mt * 16 + lr) * KPADH + kk + lk) * 2;
            ldsm4(af[mt], addr);
        }
#pragma unroll
        for (int p = 0; p < 2; p++) {
            uint32_t r[4];
            uint32_t addr = b_base + ((wn * 32 + p * 16 + lr) * KPADH + kk + lk) * 2;
            ldsm4(r, addr);
            bf[2 * p][0] = r[0];     bf[2 * p][1] = r[2];
            bf[2 * p + 1][0] = r[1]; bf[2 * p + 1][1] = r[3];
        }
    };
    auto mma_all = [&](uint32_t af[4][4], uint32_t bf[4][2]) {
#pragma unroll
        for (int mt = 0; mt < 4; mt++)
#pragma unroll
            for (int nt = 0; nt < 4; nt++)
                mma16816(c[mt][nt], af[mt], bf[nt]);
    };

#pragma unroll
    for (int s = 0; s < STG - 1; s++) {
        load_stage(s, s);
        CP_COMMIT();
    }

    uint32_t afA[4][4], bfA[4][2], afB[4][4], bfB[4][2];
    CP_WAIT(STG - 2);          // own stage-0 group retired
    __syncthreads();           // ALL threads' stage-0 copies visible
    ldsm_group(afA, bfA, smem_u, 0);   // tile 0, g0 (safe: after barrier)

    int buf = 0;
    for (int t = 0; t < KT2; t++) {
        uint32_t base = smem_u + buf * STAGE_BYTES;
        int nbuf = (buf + 1 == STG) ? 0 : buf + 1;

        ldsm_group(afB, bfB, base, 16);   // g1 of current tile (stage t synced)
        mma_all(afA, bfA);                // g0 MMAs overlap g1 ldsm latency

        if (t + 1 < KT2) CP_WAIT(1);      // own stage t+1 group retired
        mma_all(afB, bfB);                // g1 MMAs

        __syncthreads();                  // all threads' stage t+1 visible;
                                          // all reads of tile t complete
        if (t + 1 < KT2)
            ldsm_group(afA, bfA, smem_u + nbuf * STAGE_BYTES, 0);  // prefetch g0
        if (t + STG - 1 < KT2) {
            int lb = buf + (STG - 1);
            if (lb >= STG) lb -= STG;
            load_stage(t + STG - 1, lb);  // writes tile t-1's buffer (2 syncs old)
        }
        CP_COMMIT();
        buf = nbuf;
    }

    // ---------------- epilogue ----------------
    if (EPI == 2 && bn == 8) {
#pragma unroll
        for (int mt = 0; mt < 4; mt++) {
            int r0 = bm * 128 + wm * 64 + mt * 16 + gid;
            int b0 = r0 >> 12, n0 = r0 & (N_ - 1);
            int r1 = r0 + 8;
            int b1v = r1 >> 12, n1 = r1 & (N_ - 1);
#pragma unroll
            for (int nt = 0; nt < 4; nt++) {
                int col = wn * 32 + nt * 8 + tig * 2;
                if (col < 48) {
#pragma unroll
                    for (int q = 0; q < 2; q++) {
                        int cl = col + q;
                        int which = cl >> 4, h = cl & 15;
                        float p1a = (which == 0) ? g_p1[h * N_ + n0] : 0.f;
                        float p1b = (which == 0) ? g_p1[h * N_ + n1] : 0.f;
                        proj_store(c[mt][nt][q] + p1a, which, h, b0, n0);
                        proj_store(c[mt][nt][2 + q] + p1b, which, h, b1v, n1);
                    }
                }
            }
        }
        return;
    }

#pragma unroll
    for (int mt = 0; mt < 4; mt++) {
        int r0 = bm * 128 + wm * 64 + mt * 16 + gid;
#pragma unroll
        for (int nt = 0; nt < 4; nt++) {
            int col = bn * 128 + wn * 32 + nt * 8 + tig * 2;
            if (EPI == 1) {
                *(float2*)((float*)Cv + (size_t)r0 * 1024 + col) =
                    make_float2(c[mt][nt][0], c[mt][nt][1]);
                *(float2*)((float*)Cv + (size_t)(r0 + 8) * 1024 + col) =
                    make_float2(c[mt][nt][2], c[mt][nt][3]);
            } else {
                *(__half2*)((__half*)Cv + (size_t)r0 * 1024 + col) =
                    __floats2half2_rn(c[mt][nt][0], c[mt][nt][1]);
                *(__half2*)((__half*)Cv + (size_t)(r0 + 8) * 1024 + col) =
                    __floats2half2_rn(c[mt][nt][2], c[mt][nt][3]);
            }
        }
    }
}

// ---------------------------------------------------------------------------
// 5) Fused single-kernel scan: one block per (b,h); 1024 threads =
//    16 chunks x 64 a-lanes; in-block smem prefix over chunk partials.
// ---------------------------------------------------------------------------
#define SCH 16                 // chunks per block
#define SCLEN (N_ / SCH)       // 256 n per chunk

__global__ __launch_bounds__(1024) void scan_fused() {
    __shared__ float s_cv[SCH][A_];
    __shared__ float s_c[SCH];

    int bh = blockIdx.x;
    int b = bh >> 4, h = bh & 15;
    int g = threadIdx.x >> 6;          // chunk 0..15
    int a = threadIdx.x & 63;
    int n0 = g * SCLEN;

    const float* cr = g_cross + bh * N_;
    const float* dg = g_diag + bh * N_;
    const float* ex = g_extra + bh * N_;
    const float* pe = g_p2e + h * N_;

    // phase 1: chunk partial sums
    float sc = 0.f, scv = 0.f;
#pragma unroll 8
    for (int i = 0; i < SCLEN; i++) {
        int n = n0 + i;
        float cn = cr[n];
        float v = __half2float(g_valh[((size_t)(b * N_ + n) * H_ + h) * A_ + a]);
        sc += cn;
        scv = fmaf(cn, v, scv);
    }
    s_cv[g][a] = scv;
    if (a == 0) s_c[g] = sc;
    __syncthreads();

    // phase 2: exclusive prefix over chunks
    float run_cv = 0.f, run_c = 0.f;
#pragma unroll
    for (int j = 0; j < SCH; j++) {
        if (j < g) {
            run_cv += s_cv[j][a];
            run_c += s_c[j];
        }
    }

    // phase 3: rescan with carried prefix, write fp16 out
#pragma unroll 4
    for (int i = 0; i < SCLEN; i++) {
        int n = n0 + i;
        float cn = cr[n];
        float dn = dg[n];
        float peE = pe[n] * ex[n];
        size_t vidx = ((size_t)(b * N_ + n) * H_ + h) * A_ + a;
        float v = __half2float(g_valh[vidx]);
        run_cv = fmaf(cn, v, run_cv);
        run_c += cn;
        float num = fmaf(run_cv, peE, v * dn);
        float den = fmaf(run_c, peE, dn);
        g_outh[vidx] = __float2half_rn(num / den);
    }
}

// ---------------------------------------------------------------------------
// Launcher
// ---------------------------------------------------------------------------
extern "C" void kernel_launch(void* const* d_in, const int* in_sizes, int n_in,
                              void* d_out, int out_size) {
    const float* x  = (const float*)d_in[0];
    const float* k1 = (const float*)d_in[1];
    const float* k2 = (const float*)d_in[2];
    const float* k3 = (const float*)d_in[3];
    const float* a1 = (const float*)d_in[4];
    const float* a2 = (const float*)d_in[5];
    const float* b1 = (const float*)d_in[6];
    const float* b2 = (const float*)d_in[7];
    const float* cc = (const float*)d_in[8];
    const float* vw = (const float*)d_in[9];
    const float* ow = (const float*)d_in[10];
    float* out = (float*)d_out;

    void *p_wve, *p_woh, *p_valh, *p_outh, *p_xh;
    cudaGetSymbolAddress(&p_wve, g_wv_e);
    cudaGetSymbolAddress(&p_woh, g_wo_h);
    cudaGetSymbolAddress(&p_valh, g_valh);
    cudaGetSymbolAddress(&p_outh, g_outh);
    cudaGetSymbolAddress(&p_xh, g_xh);

    cudaFuncSetAttribute(gemm_f16<2>, cudaFuncAttributeMaxDynamicSharedMemorySize, GSMEM);
    cudaFuncSetAttribute(gemm_f16<1>, cudaFuncAttributeMaxDynamicSharedMemorySize, GSMEM);

    convert_x<<<M_ * W_ / (256 * 8), 256>>>(x);
    transpose_wv<<<dim3(32, 2, 16), dim3(32, 8)>>>(vw);
    fill_proj_rows<<<512, 256>>>(k1, k2, k3);
    transpose_wo<<<2048, 256>>>(ow);
    pos_kernel<<<(H_ * N_) / 256, 256>>>(a1, a2, b1, b2, cc);

    // GEMM1 (fused proj): values cols 0..1023 -> g_valh; tile bn==8 -> exp scatter
    gemm_f16<2><<<dim3(9, 128), 256, GSMEM>>>((const __half*)p_xh,
                                              (const __half*)p_wve, p_valh);

    scan_fused<<<B_ * H_, 1024>>>();

    // result = outh @ Wo^T -> d_out (f32)
    gemm_f16<1><<<dim3(8, 128), 256, GSMEM>>>((const __half*)p_outh,
                                              (const __half*)p_woh, out);
}

// round 12
// speedup vs baseline: 7.0021x; 1.1160x over previous
#include <cuda_runtime.h>
#include <cuda_fp16.h>
#include <math.h>
#include <stdint.h>

// Problem shapes (fixed)
#define B_ 4
#define N_ 4096
#define W_ 1024
#define H_ 16
#define A_ 64
#define HA_ 1024           // H_*A_
#define M_ 16384           // B_*N_
#define NB1 1152           // GEMM1 extended N (1024 values + 48 proj + 80 pad)

// ---------------------------------------------------------------------------
// Scratch (no allocations allowed -> __device__ globals)
// ---------------------------------------------------------------------------
__device__ __half g_valh[M_ * HA_];         // 32 MB (GEMM1 out, fp16)
__device__ __half g_outh[M_ * HA_];         // 32 MB (GEMM2 in, fp16)
__device__ __half g_xh[M_ * W_];            // fp16 x, 32 MB
__device__ __half g_wv_e[NB1 * W_];         // extended GEMM1 B: 2.25 MB
__device__ __half g_wo_h[W_ * HA_];         // 2 MB
__device__ float g_cross[B_ * H_ * N_];
__device__ float g_diag [B_ * H_ * N_];
__device__ float g_extra[B_ * H_ * N_];
__device__ float g_p1 [H_ * N_];
__device__ float g_p2e[H_ * N_];

__device__ __forceinline__ uint32_t s2u(const void* p) {
    uint32_t r;
    asm("{ .reg .u64 t; cvta.to.shared.u64 t, %1; cvt.u32.u64 %0, t; }" : "=r"(r) : "l"(p));
    return r;
}
__device__ __forceinline__ void cp16(uint32_t dst, const void* src) {
    asm volatile("cp.async.cg.shared.global [%0], [%1], 16;" :: "r"(dst), "l"(src));
}
#define CP_COMMIT() asm volatile("cp.async.commit_group;" ::: "memory")
#define CP_WAIT(n)  asm volatile("cp.async.wait_group %0;" :: "n"(n) : "memory")

// ---------------------------------------------------------------------------
// 0) x -> fp16 convert (feeds GEMM1 A)
// ---------------------------------------------------------------------------
__global__ void convert_x(const float* __restrict__ x) {
    size_t i = ((size_t)blockIdx.x * blockDim.x + threadIdx.x) * 8;
    float4 v1 = *(const float4*)(x + i);
    float4 v2 = *(const float4*)(x + i + 4);
    __half2 h0 = __floats2half2_rn(v1.x, v1.y);
    __half2 h1 = __floats2half2_rn(v1.z, v1.w);
    __half2 h2 = __floats2half2_rn(v2.x, v2.y);
    __half2 h3 = __floats2half2_rn(v2.z, v2.w);
    *(uint4*)(g_xh + i) = make_uint4(*(uint32_t*)&h0, *(uint32_t*)&h1,
                                     *(uint32_t*)&h2, *(uint32_t*)&h3);
}

// ---------------------------------------------------------------------------
// 1a) Wv transpose into extended B rows 0..1023, smem tiled, coalesced
// ---------------------------------------------------------------------------
__global__ void transpose_wv(const float* __restrict__ vw) {
    __shared__ float tile[32][33];
    int h = blockIdx.z;
    int w0 = blockIdx.x * 32;
    int a0 = blockIdx.y * 32;
    int tx = threadIdx.x, ty = threadIdx.y;     // 32 x 8
#pragma unroll
    for (int i = 0; i < 4; i++) {
        int w = w0 + ty + i * 8;
        tile[ty + i * 8][tx] = vw[((h << 10) + w) * 64 + a0 + tx];
    }
    __syncthreads();
#pragma unroll
    for (int i = 0; i < 4; i++) {
        int a = a0 + ty + i * 8;
        g_wv_e[((h << 6) + a) * 1024 + w0 + tx] = __float2half_rn(tile[tx][ty + i * 8]);
    }
}

// ---------------------------------------------------------------------------
// 1c) Extended B rows 1024..1151: k1/k2/k3 heads then zero pad
// ---------------------------------------------------------------------------
__global__ void fill_proj_rows(const float* __restrict__ k1,
                               const float* __restrict__ k2,
                               const float* __restrict__ k3) {
    int idx = blockIdx.x * blockDim.x + threadIdx.x;
    int j = idx >> 10;          // 0..127 (row - 1024)
    int w = idx & 1023;
    __half v = __float2half(0.f);
    if (j < 48) {
        const float* kk = (j < 16) ? k1 : ((j < 32) ? k2 : k3);
        v = __float2half_rn(kk[(j & 15) * W_ + w]);
    }
    g_wv_e[(size_t)(1024 + j) * 1024 + w] = v;
}

// ---------------------------------------------------------------------------
// 1b) Wo permuted copy
// ---------------------------------------------------------------------------
__global__ void transpose_wo(const float* __restrict__ ow) {
    int i2 = (blockIdx.x * blockDim.x + threadIdx.x) * 2;
    int a = i2 & 63;
    int hq = (i2 >> 6) & 15;
    int w = i2 >> 10;
    float2 v = *(const float2*)(ow + (size_t)(((hq << 10) + w) << 6) + a);
    *(__half2*)(g_wo_h + i2) = __floats2half2_rn(v.x, v.y);
}

// ---------------------------------------------------------------------------
// 2) Positional
// ---------------------------------------------------------------------------
__global__ void pos_kernel(const float* __restrict__ a1, const float* __restrict__ a2,
                           const float* __restrict__ b1, const float* __restrict__ b2,
                           const float* __restrict__ cc) {
    int idx = blockIdx.x * blockDim.x + threadIdx.x;
    int h = idx >> 12;
    int n = idx & (N_ - 1);
    float nv = (float)n * (1.0f / 4095.0f);
    float s1 = 0.f, s2 = 0.f;
#pragma unroll 8
    for (int p = 0; p < 64; p++) {
        float cp = cc[h * 64 + p];
        s1 += sinf(fmaf(a1[h * 64 + p], nv, b1[h * 64 + p])) * cp;
        s2 += sinf(fmaf(a2[h * 64 + p], nv, b2[h * 64 + p])) * cp;
    }
    g_p1[idx] = s1;
    s2 = fminf(fmaxf(s2, -20.f), 20.f);
    g_p2e[idx] = expf(s2);
}

// ---------------------------------------------------------------------------
// 4/7) fp16 mma.m16n8k16 GEMM, cp.async 4-stage pipeline, prefetch after sync.
//      EPI: 1 = float C, 2 = half C + fused proj tile at bn==8
// ---------------------------------------------------------------------------
#define BK 32
#define KPADH 40
#define KT2 (1024 / BK)
#define STG 4
#define HALF_BYTES (128 * KPADH * 2)
#define STAGE_BYTES (2 * HALF_BYTES)
#define GSMEM (STG * STAGE_BYTES)

__device__ __forceinline__ void mma16816(float* c, const uint32_t* a, const uint32_t* b) {
    asm volatile(
        "mma.sync.aligned.m16n8k16.row.col.f32.f16.f16.f32 "
        "{%0,%1,%2,%3}, {%4,%5,%6,%7}, {%8,%9}, {%0,%1,%2,%3};"
        : "+f"(c[0]), "+f"(c[1]), "+f"(c[2]), "+f"(c[3])
        : "r"(a[0]), "r"(a[1]), "r"(a[2]), "r"(a[3]), "r"(b[0]), "r"(b[1]));
}
__device__ __forceinline__ void ldsm4(uint32_t* r, uint32_t addr) {
    asm volatile("ldmatrix.sync.aligned.m8n8.x4.shared.b16 {%0,%1,%2,%3}, [%4];"
                 : "=r"(r[0]), "=r"(r[1]), "=r"(r[2]), "=r"(r[3]) : "r"(addr));
}

__device__ __forceinline__ void proj_store(float s, int which, int h, int b, int n) {
    s = fminf(fmaxf(s, -20.f), 20.f);
    s = expf(s);
    int off = (b * H_ + h) * N_ + n;
    if (which == 0)      g_cross[off] = s;
    else if (which == 1) g_diag[off]  = s;
    else                 g_extra[off] = s;
}

template <int EPI>
__global__ __launch_bounds__(256, 2) void gemm_f16(const __half* __restrict__ A,
                                                   const __half* __restrict__ Bt,
                                                   void* __restrict__ Cv) {
    extern __shared__ __align__(16) char smem[];
    uint32_t smem_u = s2u(smem);

    int tid = threadIdx.x;
    int lane = tid & 31, wid = tid >> 5;
    int wm = wid >> 2;
    int wn = wid & 3;
    int gid = lane >> 2;
    int tig = lane & 3;
    int lr = lane & 15;
    int lk = (lane >> 4) << 3;

    int bn = blockIdx.x, bm = blockIdx.y;
    const __half* Ag = A + (size_t)(bm * 128) * 1024;
    const __half* Bg = Bt + (size_t)(bn * 128) * 1024;

    int c0row = tid >> 2;
    int c0k = (tid & 3) * 8;

    float c[4][4][4];
#pragma unroll
    for (int i = 0; i < 4; i++)
#pragma unroll
        for (int j = 0; j < 4; j++)
#pragma unroll
            for (int q = 0; q < 4; q++) c[i][j][q] = 0.f;

    auto load_stage = [&](int t, int s) {
        int k0 = t * BK;
        uint32_t base = smem_u + s * STAGE_BYTES;
#pragma unroll
        for (int i = 0; i < 2; i++) {
            int row = c0row + i * 64;
            uint32_t off = (uint32_t)(row * (KPADH * 2) + c0k * 2);
            cp16(base + off, Ag + (size_t)row * 1024 + k0 + c0k);
            cp16(base + HALF_BYTES + off, Bg + (size_t)row * 1024 + k0 + c0k);
        }
    };
    auto ldsm_group = [&](uint32_t af[4][4], uint32_t bf[4][2],
                          uint32_t a_base, int kk) {
        uint32_t b_base = a_base + HALF_BYTES;
#pragma unroll
        for (int mt = 0; mt < 4; mt++) {
            uint32_t addr = a_base + ((wm * 64 + mt * 16 + lr) * KPADH + kk + lk) * 2;
            ldsm4(af[mt], addr);
        }
#pragma unroll
        for (int p = 0; p < 2; p++) {
            uint32_t r[4];
            uint32_t addr = b_base + ((wn * 32 + p * 16 + lr) * KPADH + kk + lk) * 2;
            ldsm4(r, addr);
            bf[2 * p][0] = r[0];     bf[2 * p][1] = r[2];
            bf[2 * p + 1][0] = r[1]; bf[2 * p + 1][1] = r[3];
        }
    };
    auto mma_all = [&](uint32_t af[4][4], uint32_t bf[4][2]) {
#pragma unroll
        for (int mt = 0; mt < 4; mt++)
#pragma unroll
            for (int nt = 0; nt < 4; nt++)
                mma16816(c[mt][nt], af[mt], bf[nt]);
    };

#pragma unroll
    for (int s = 0; s < STG - 1; s++) {
        load_stage(s, s);
        CP_COMMIT();
    }

    uint32_t afA[4][4], bfA[4][2], afB[4][4], bfB[4][2];
    CP_WAIT(STG - 2);          // own stage-0 group retired
    __syncthreads();           // ALL threads' stage-0 copies visible
    ldsm_group(afA, bfA, smem_u, 0);   // tile 0, g0

    int buf = 0;
    for (int t = 0; t < KT2; t++) {
        uint32_t base = smem_u + buf * STAGE_BYTES;
        int nbuf = (buf + 1 == STG) ? 0 : buf + 1;

        ldsm_group(afB, bfB, base, 16);   // g1 of current tile
        mma_all(afA, bfA);                // g0 MMAs overlap g1 ldsm latency

        if (t + 1 < KT2) CP_WAIT(1);      // own stage t+1 group retired
        mma_all(afB, bfB);                // g1 MMAs

        __syncthreads();                  // stage t+1 visible to all threads
        if (t + 1 < KT2)
            ldsm_group(afA, bfA, smem_u + nbuf * STAGE_BYTES, 0);  // prefetch g0
        if (t + STG - 1 < KT2) {
            int lb = buf + (STG - 1);
            if (lb >= STG) lb -= STG;
            load_stage(t + STG - 1, lb);
        }
        CP_COMMIT();
        buf = nbuf;
    }

    // ---------------- epilogue ----------------
    if (EPI == 2 && bn == 8) {
#pragma unroll
        for (int mt = 0; mt < 4; mt++) {
            int r0 = bm * 128 + wm * 64 + mt * 16 + gid;
            int b0 = r0 >> 12, n0 = r0 & (N_ - 1);
            int r1 = r0 + 8;
            int b1v = r1 >> 12, n1 = r1 & (N_ - 1);
#pragma unroll
            for (int nt = 0; nt < 4; nt++) {
                int col = wn * 32 + nt * 8 + tig * 2;
                if (col < 48) {
#pragma unroll
                    for (int q = 0; q < 2; q++) {
                        int cl = col + q;
                        int which = cl >> 4, h = cl & 15;
                        float p1a = (which == 0) ? g_p1[h * N_ + n0] : 0.f;
                        float p1b = (which == 0) ? g_p1[h * N_ + n1] : 0.f;
                        proj_store(c[mt][nt][q] + p1a, which, h, b0, n0);
                        proj_store(c[mt][nt][2 + q] + p1b, which, h, b1v, n1);
                    }
                }
            }
        }
        return;
    }

#pragma unroll
    for (int mt = 0; mt < 4; mt++) {
        int r0 = bm * 128 + wm * 64 + mt * 16 + gid;
#pragma unroll
        for (int nt = 0; nt < 4; nt++) {
            int col = bn * 128 + wn * 32 + nt * 8 + tig * 2;
            if (EPI == 1) {
                *(float2*)((float*)Cv + (size_t)r0 * 1024 + col) =
                    make_float2(c[mt][nt][0], c[mt][nt][1]);
                *(float2*)((float*)Cv + (size_t)(r0 + 8) * 1024 + col) =
                    make_float2(c[mt][nt][2], c[mt][nt][3]);
            } else {
                *(__half2*)((__half*)Cv + (size_t)r0 * 1024 + col) =
                    __floats2half2_rn(c[mt][nt][0], c[mt][nt][1]);
                *(__half2*)((__half*)Cv + (size_t)(r0 + 8) * 1024 + col) =
                    __floats2half2_rn(c[mt][nt][2], c[mt][nt][3]);
            }
        }
    }
}

// ---------------------------------------------------------------------------
// 5) Fused scan, occupancy-split: grid = 64 bh x 4 a-slices = 256 blocks.
//    Each block: 1024 threads = 64 chunks x 16 a-lanes; chunk = 64 n.
// ---------------------------------------------------------------------------
#define SCH 64                 // chunks per block
#define SCLEN (N_ / SCH)       // 64 n per chunk
#define ALANES 16              // a-lanes per block (A_/4)

__global__ __launch_bounds__(1024) void scan_fused() {
    __shared__ float s_cv[SCH][ALANES];
    __shared__ float s_c[SCH];

    int bh = blockIdx.x >> 2;          // 0..63
    int abase = (blockIdx.x & 3) * ALANES;
    int b = bh >> 4, h = bh & 15;
    int g = threadIdx.x >> 4;          // chunk 0..63
    int a = abase + (threadIdx.x & 15);
    int n0 = g * SCLEN;

    const float* cr = g_cross + bh * N_;
    const float* dg = g_diag + bh * N_;
    const float* ex = g_extra + bh * N_;
    const float* pe = g_p2e + h * N_;

    // phase 1: chunk partial sums
    float sc = 0.f, scv = 0.f;
#pragma unroll 8
    for (int i = 0; i < SCLEN; i++) {
        int n = n0 + i;
        float cn = cr[n];
        float v = __half2float(g_valh[((size_t)(b * N_ + n) * H_ + h) * A_ + a]);
        sc += cn;
        scv = fmaf(cn, v, scv);
    }
    s_cv[g][threadIdx.x & 15] = scv;
    if ((threadIdx.x & 15) == 0) s_c[g] = sc;
    __syncthreads();

    // phase 2: exclusive prefix over chunks
    float run_cv = 0.f, run_c = 0.f;
#pragma unroll
    for (int j = 0; j < SCH; j++) {
        if (j < g) {
            run_cv += s_cv[j][threadIdx.x & 15];
            run_c += s_c[j];
        }
    }

    // phase 3: rescan with carried prefix, write fp16 out
#pragma unroll 8
    for (int i = 0; i < SCLEN; i++) {
        int n = n0 + i;
        float cn = cr[n];
        float dn = dg[n];
        float peE = pe[n] * ex[n];
        size_t vidx = ((size_t)(b * N_ + n) * H_ + h) * A_ + a;
        float v = __half2float(g_valh[vidx]);
        run_cv = fmaf(cn, v, run_cv);
        run_c += cn;
        float num = fmaf(run_cv, peE, v * dn);
        float den = fmaf(run_c, peE, dn);
        g_outh[vidx] = __float2half_rn(num / den);
    }
}

// ---------------------------------------------------------------------------
// Launcher
// ---------------------------------------------------------------------------
extern "C" void kernel_launch(void* const* d_in, const int* in_sizes, int n_in,
                              void* d_out, int out_size) {
    const float* x  = (const float*)d_in[0];
    const float* k1 = (const float*)d_in[1];
    const float* k2 = (const float*)d_in[2];
    const float* k3 = (const float*)d_in[3];
    const float* a1 = (const float*)d_in[4];
    const float* a2 = (const float*)d_in[5];
    const float* b1 = (const float*)d_in[6];
    const float* b2 = (const float*)d_in[7];
    const float* cc = (const float*)d_in[8];
    const float* vw = (const float*)d_in[9];
    const float* ow = (const float*)d_in[10];
    float* out = (float*)d_out;

    void *p_wve, *p_woh, *p_valh, *p_outh, *p_xh;
    cudaGetSymbolAddress(&p_wve, g_wv_e);
    cudaGetSymbolAddress(&p_woh, g_wo_h);
    cudaGetSymbolAddress(&p_valh, g_valh);
    cudaGetSymbolAddress(&p_outh, g_outh);
    cudaGetSymbolAddress(&p_xh, g_xh);

    cudaFuncSetAttribute(gemm_f16<2>, cudaFuncAttributeMaxDynamicSharedMemorySize, GSMEM);
    cudaFuncSetAttribute(gemm_f16<1>, cudaFuncAttributeMaxDynamicSharedMemorySize, GSMEM);

    convert_x<<<M_ * W_ / (256 * 8), 256>>>(x);
    transpose_wv<<<dim3(32, 2, 16), dim3(32, 8)>>>(vw);
    fill_proj_rows<<<512, 256>>>(k1, k2, k3);
    transpose_wo<<<2048, 256>>>(ow);
    pos_kernel<<<(H_ * N_) / 256, 256>>>(a1, a2, b1, b2, cc);

    // GEMM1 (fused proj): values cols 0..1023 -> g_valh; tile bn==8 -> exp scatter
    gemm_f16<2><<<dim3(9, 128), 256, GSMEM>>>((const __half*)p_xh,
                                              (const __half*)p_wve, p_valh);

    scan_fused<<<B_ * H_ * 4, 1024>>>();

    // result = outh @ Wo^T -> d_out (f32)
    gemm_f16<1><<<dim3(8, 128), 256, GSMEM>>>((const __half*)p_outh,
                                              (const __half*)p_woh, out);
}